// round 7
// baseline (speedup 1.0000x reference)
#include <cuda_runtime.h>

#define NWIN 16384      // B*NW = 256*64 windows
#define SEQT 32         // WIN
#define FEATN 16
#define HID 64
#define GATES 256       // 4*HID
#define EMB 128

// -------- scratch (device globals: allocation-free rule) --------
__device__ float g_lo[(size_t)NWIN * SEQT * EMB];      // bilstm output, 268MB
__device__ float g_y1[(size_t)NWIN * SEQT * 384];      // q|k|v, 805MB
__device__ float g_pooled[(size_t)NWIN * EMB];         // 8MB
__device__ float g_seq[(size_t)256 * 8192];            // 8MB

__device__ __forceinline__ float sigmf(float x) { return 1.f / (1.f + __expf(-x)); }

// ================= 1. BiLSTM (fwd+bwd fused, one window per block) =================
__global__ __launch_bounds__(512) void lstm_kernel(
    const float* __restrict__ x,
    const float* __restrict__ wihf, const float* __restrict__ whhf,
    const float* __restrict__ bihf, const float* __restrict__ bhhf,
    const float* __restrict__ wihb, const float* __restrict__ whhb,
    const float* __restrict__ bihb, const float* __restrict__ bhhb)
{
    int n   = blockIdx.x;
    int tid = threadIdx.x;
    int dir = tid >> 8;     // 0=fwd warps, 1=bwd warps (no intra-warp divergence)
    int g   = tid & 255;    // gate element

    __shared__ float xs[SEQT * FEATN];
    __shared__ float h_sh[2][HID];
    __shared__ float g_sh[2][GATES];

    const float* wih = dir ? wihb : wihf;
    const float* whh = dir ? whhb : whhf;
    const float* bih = dir ? bihb : bihf;
    const float* bhh = dir ? bhhb : bhhf;

    // window n is contiguous: x[n*512 + t*16 + f]
    for (int i = tid; i < SEQT * FEATN; i += 512) xs[i] = x[(size_t)n * 512 + i];

    float wi[FEATN];
    #pragma unroll
    for (int f = 0; f < FEATN; f++) wi[f] = wih[g * FEATN + f];
    float wh[HID];
    #pragma unroll
    for (int k = 0; k < HID; k++) wh[k] = whh[g * HID + k];
    float bias = bih[g] + bhh[g];

    if (g < HID) h_sh[dir][g] = 0.f;
    float c = 0.f;
    __syncthreads();

    for (int s = 0; s < SEQT; s++) {
        int t = dir ? (31 - s) : s;
        float acc = bias;
        #pragma unroll
        for (int f = 0; f < FEATN; f++) acc += xs[t * FEATN + f] * wi[f];
        #pragma unroll
        for (int k = 0; k < HID; k++) acc += h_sh[dir][k] * wh[k];
        g_sh[dir][g] = acc;
        __syncthreads();
        if (g < HID) {
            float ig = sigmf(g_sh[dir][g]);
            float fg = sigmf(g_sh[dir][HID + g]);
            float gg = tanhf(g_sh[dir][2 * HID + g]);
            float og = sigmf(g_sh[dir][3 * HID + g]);
            c = fg * c + ig * gg;
            float h = og * tanhf(c);
            h_sh[dir][g] = h;
            g_lo[((size_t)n * SEQT + t) * EMB + dir * HID + g] = h;
        }
        __syncthreads();
    }
}

// ================= 2. QKV GEMM: Y1[524288,384] = LO[524288,128] @ W^T + b ==========
__global__ __launch_bounds__(256) void qkv_gemm(const float* __restrict__ W,
                                                const float* __restrict__ bias)
{
    __shared__ float As[64][65];
    __shared__ float Bs[64][65];
    int m0 = blockIdx.y * 64;
    int n0 = blockIdx.x * 64;
    int tid = threadIdx.x;
    int tx = tid & 15, ty = tid >> 4;

    float acc[4][4];
    #pragma unroll
    for (int i = 0; i < 4; i++)
        #pragma unroll
        for (int j = 0; j < 4; j++) acc[i][j] = 0.f;

    for (int kt = 0; kt < 128; kt += 64) {
        __syncthreads();
        #pragma unroll
        for (int i = tid; i < 4096; i += 256) {
            int r = i >> 6, cc = i & 63;
            As[r][cc] = g_lo[(size_t)(m0 + r) * 128 + kt + cc];
            Bs[r][cc] = W[(n0 + r) * 128 + kt + cc];
        }
        __syncthreads();
        #pragma unroll 16
        for (int k = 0; k < 64; k++) {
            float a[4], b[4];
            #pragma unroll
            for (int i = 0; i < 4; i++) a[i] = As[ty + 16 * i][k];
            #pragma unroll
            for (int j = 0; j < 4; j++) b[j] = Bs[tx + 16 * j][k];
            #pragma unroll
            for (int i = 0; i < 4; i++)
                #pragma unroll
                for (int j = 0; j < 4; j++) acc[i][j] += a[i] * b[j];
        }
    }
    #pragma unroll
    for (int i = 0; i < 4; i++) {
        int m = m0 + ty + 16 * i;
        #pragma unroll
        for (int j = 0; j < 4; j++) {
            int nn = n0 + tx + 16 * j;
            g_y1[(size_t)m * 384 + nn] = acc[i][j] + bias[nn];
        }
    }
}

// ===== 3. Self-attn + out-proj + proj + mean-pool, fused via mean-commute trick ====
__global__ __launch_bounds__(128) void attn_kernel(
    const float* __restrict__ out_w, const float* __restrict__ out_b,
    const float* __restrict__ proj_w, const float* __restrict__ proj_b)
{
    int n = blockIdx.x;
    int tid = threadIdx.x;
    __shared__ float k_sh[SEQT * EMB];
    __shared__ float v_sh[SEQT * EMB];
    __shared__ float abar[EMB];     // [h*32 + k]: mean_t softmax weights
    __shared__ float oav[EMB];
    __shared__ float samean[EMB];

    const float* y = g_y1 + (size_t)n * SEQT * 384;
    for (int i = tid; i < SEQT * EMB; i += 128) {
        int t = i >> 7, cc = i & 127;
        k_sh[i] = y[t * 384 + 128 + cc];
        v_sh[i] = y[t * 384 + 256 + cc];
    }
    abar[tid] = 0.f;
    __syncthreads();

    int h = tid >> 5, t = tid & 31;   // one (head, query-token) row per thread
    float q[32];
    #pragma unroll
    for (int d = 0; d < 32; d++) q[d] = y[t * 384 + h * 32 + d];

    float s[32];
    float mx = -1e30f;
    #pragma unroll
    for (int kk = 0; kk < 32; kk++) {
        float a = 0.f;
        #pragma unroll
        for (int d = 0; d < 32; d++) a += q[d] * k_sh[kk * EMB + h * 32 + d];
        a *= 0.1767766953f;           // 1/sqrt(32)
        s[kk] = a;
        mx = fmaxf(mx, a);
    }
    float sum = 0.f;
    #pragma unroll
    for (int kk = 0; kk < 32; kk++) { float e = __expf(s[kk] - mx); s[kk] = e; sum += e; }
    float inv = 1.f / (sum * 32.f);   // softmax + mean over t folded
    #pragma unroll
    for (int k0 = 0; k0 < 32; k0++) {
        int kk = (k0 + t) & 31;       // stagger lanes -> conflict-free smem atomics
        atomicAdd(&abar[h * 32 + kk], s[kk] * inv);
    }
    __syncthreads();

    // mean attention output channel c = tid
    float o = 0.f;
    #pragma unroll
    for (int kk = 0; kk < 32; kk++) o += abar[(tid >> 5) * 32 + kk] * v_sh[kk * EMB + tid];
    oav[tid] = o;
    __syncthreads();

    float sm = out_b[tid];
    #pragma unroll 8
    for (int cc = 0; cc < 128; cc++) sm += oav[cc] * out_w[tid * 128 + cc];
    samean[tid] = sm;
    __syncthreads();

    float p = proj_b[tid];
    #pragma unroll 8
    for (int cc = 0; cc < 128; cc++) p += samean[cc] * proj_w[tid * 128 + cc];
    g_pooled[(size_t)n * EMB + tid] = p;
}

// ================= 4. Cross-attention (q-len 1, <=4 neighbors) + LayerNorm =========
__global__ __launch_bounds__(128) void cross_kernel(
    const float* __restrict__ ca_in_w, const float* __restrict__ ca_in_b,
    const float* __restrict__ ca_out_w, const float* __restrict__ ca_out_b,
    const float* __restrict__ lng, const float* __restrict__ lnb)
{
    int ci = blockIdx.x >> 8;     // weights reused across consecutive blocks
    int b  = blockIdx.x & 255;
    int tid = threadIdx.x;

    int left  = ci - 2 > 0 ? ci - 2 : 0;
    int right = ci + 3 < 64 ? ci + 3 : 64;
    int idx[4]; int nbr = 0;
    for (int i = left; i < right; i++) if (i != ci) idx[nbr++] = i;

    __shared__ float cen[128], ctx[4 * 128];
    __shared__ float q_sh[128], k_sh2[4 * 128], v_sh2[4 * 128];
    __shared__ float o_sh[128], sc_sh[16], a_w[16], r_sh[128], stats[2];

    cen[tid] = g_pooled[((size_t)b * 64 + ci) * 128 + tid];
    #pragma unroll
    for (int j = 0; j < 4; j++)
        ctx[j * 128 + tid] = (j < nbr) ? g_pooled[((size_t)b * 64 + idx[j]) * 128 + tid] : 0.f;
    __syncthreads();

    const float* Wq = ca_in_w + (size_t)ci * 384 * 128 + (size_t)tid * 128;
    const float* Wk = Wq + 128 * 128;
    const float* Wv = Wq + 2 * 128 * 128;
    float accq = 0.f, acck[4] = {0, 0, 0, 0}, accv[4] = {0, 0, 0, 0};
    for (int c = 0; c < 128; c++) {
        float ce = cen[c];
        accq += Wq[c] * ce;
        float wk = Wk[c], wv = Wv[c];
        #pragma unroll
        for (int j = 0; j < 4; j++) {
            float xc = ctx[j * 128 + c];
            acck[j] += wk * xc;
            accv[j] += wv * xc;
        }
    }
    q_sh[tid] = accq + ca_in_b[ci * 384 + tid];
    float bk = ca_in_b[ci * 384 + 128 + tid];
    float bv = ca_in_b[ci * 384 + 256 + tid];
    #pragma unroll
    for (int j = 0; j < 4; j++) {
        k_sh2[j * 128 + tid] = acck[j] + bk;
        v_sh2[j * 128 + tid] = accv[j] + bv;
    }
    __syncthreads();

    if (tid < 16) {
        int h = tid >> 2, j = tid & 3;
        float sv = 0.f;
        if (j < nbr) {
            #pragma unroll
            for (int d = 0; d < 32; d++) sv += q_sh[h * 32 + d] * k_sh2[j * 128 + h * 32 + d];
            sv *= 0.1767766953f;
        }
        sc_sh[tid] = sv;
    }
    __syncthreads();
    if (tid < 4) {
        float mx = -1e30f;
        for (int j = 0; j < nbr; j++) mx = fmaxf(mx, sc_sh[tid * 4 + j]);
        float e[4]; float sum = 0.f;
        for (int j = 0; j < nbr; j++) { e[j] = __expf(sc_sh[tid * 4 + j] - mx); sum += e[j]; }
        #pragma unroll
        for (int j = 0; j < 4; j++) a_w[tid * 4 + j] = (j < nbr) ? e[j] / sum : 0.f;
    }
    __syncthreads();

    int h = tid >> 5;
    float o = 0.f;
    #pragma unroll
    for (int j = 0; j < 4; j++) o += a_w[h * 4 + j] * v_sh2[j * 128 + tid];
    o_sh[tid] = o;
    __syncthreads();

    const float* Wo = ca_out_w + (size_t)ci * 128 * 128 + (size_t)tid * 128;
    float acc = ca_out_b[ci * 128 + tid];
    for (int c = 0; c < 128; c++) acc += Wo[c] * o_sh[c];
    float r = acc + cen[tid];       // residual
    r_sh[tid] = r;
    __syncthreads();

    if (tid < 32) {
        float p = r_sh[tid] + r_sh[tid + 32] + r_sh[tid + 64] + r_sh[tid + 96];
        #pragma unroll
        for (int off = 16; off > 0; off >>= 1) p += __shfl_xor_sync(0xffffffffu, p, off);
        if (tid == 0) stats[0] = p * (1.f / 128.f);
    }
    __syncthreads();
    float m = stats[0];
    if (tid < 32) {
        float d0 = r_sh[tid] - m, d1 = r_sh[tid + 32] - m;
        float d2 = r_sh[tid + 64] - m, d3 = r_sh[tid + 96] - m;
        float p = d0 * d0 + d1 * d1 + d2 * d2 + d3 * d3;
        #pragma unroll
        for (int off = 16; off > 0; off >>= 1) p += __shfl_xor_sync(0xffffffffu, p, off);
        if (tid == 0) stats[1] = p * (1.f / 128.f);
    }
    __syncthreads();
    float yv = (r - m) * rsqrtf(stats[1] + 1e-5f) * lng[ci * 128 + tid] + lnb[ci * 128 + tid];
    g_seq[(size_t)b * 8192 + ci * 128 + tid] = yv;
}

// ================= 5. Final MLP: relu(seq@fd1^T+b) @ fd2^T + b =====================
__global__ __launch_bounds__(256) void mlp_kernel(
    const float* __restrict__ fd1_w, const float* __restrict__ fd1_b,
    const float* __restrict__ fd2_w, const float* __restrict__ fd2_b,
    float* __restrict__ out)
{
    int b = blockIdx.x;
    int tid = threadIdx.x;
    __shared__ float s_sh[8192];
    __shared__ float h1[64];
    for (int i = tid; i < 8192; i += 256) s_sh[i] = g_seq[(size_t)b * 8192 + i];
    __syncthreads();

    int w = tid >> 5, l = tid & 31;
    for (int j = w; j < 64; j += 8) {
        float acc = 0.f;
        const float* row = fd1_w + (size_t)j * 8192;
        for (int c = l; c < 8192; c += 32) acc += row[c] * s_sh[c];
        #pragma unroll
        for (int off = 16; off > 0; off >>= 1) acc += __shfl_xor_sync(0xffffffffu, acc, off);
        if (l == 0) h1[j] = fmaxf(acc + fd1_b[j], 0.f);
    }
    __syncthreads();
    if (tid < 5) {
        float o = fd2_b[tid];
        #pragma unroll
        for (int j = 0; j < 64; j++) o += fd2_w[tid * 64 + j] * h1[j];
        out[b * 5 + tid] = o;
    }
}

// =================================== launch ========================================
extern "C" void kernel_launch(void* const* d_in, const int* in_sizes, int n_in,
                              void* d_out, int out_size)
{
    const float* x        = (const float*)d_in[0];
    const float* wihf     = (const float*)d_in[1];
    const float* whhf     = (const float*)d_in[2];
    const float* bihf     = (const float*)d_in[3];
    const float* bhhf     = (const float*)d_in[4];
    const float* wihb     = (const float*)d_in[5];
    const float* whhb     = (const float*)d_in[6];
    const float* bihb     = (const float*)d_in[7];
    const float* bhhb     = (const float*)d_in[8];
    const float* sa_in_w  = (const float*)d_in[9];
    const float* sa_in_b  = (const float*)d_in[10];
    const float* sa_out_w = (const float*)d_in[11];
    const float* sa_out_b = (const float*)d_in[12];
    const float* proj_w   = (const float*)d_in[13];
    const float* proj_b   = (const float*)d_in[14];
    const float* ca_in_w  = (const float*)d_in[15];
    const float* ca_in_b  = (const float*)d_in[16];
    const float* ca_out_w = (const float*)d_in[17];
    const float* ca_out_b = (const float*)d_in[18];
    const float* ln_g     = (const float*)d_in[19];
    const float* ln_b     = (const float*)d_in[20];
    const float* fd1_w    = (const float*)d_in[21];
    const float* fd1_b    = (const float*)d_in[22];
    const float* fd2_w    = (const float*)d_in[23];
    const float* fd2_b    = (const float*)d_in[24];

    lstm_kernel<<<NWIN, 512>>>(x, wihf, whhf, bihf, bhhf, wihb, whhb, bihb, bhhb);

    dim3 g2(6, 8192);   // N tiles x M tiles; x-fastest keeps A-tiles hot in L2
    qkv_gemm<<<g2, 256>>>(sa_in_w, sa_in_b);

    attn_kernel<<<NWIN, 128>>>(sa_out_w, sa_out_b, proj_w, proj_b);

    cross_kernel<<<NWIN, 128>>>(ca_in_w, ca_in_b, ca_out_w, ca_out_b, ln_g, ln_b);

    mlp_kernel<<<256, 256>>>(fd1_w, fd1_b, fd2_w, fd2_b, (float*)d_out);
}

// round 8
// speedup vs baseline: 1.5673x; 1.5673x over previous
#include <cuda_runtime.h>

#define NWIN 16384      // B*NW = 256*64 windows
#define SEQT 32         // WIN
#define FEATN 16
#define HID 64
#define GATES 256       // 4*HID
#define EMB 128

// -------- scratch (device globals: allocation-free rule) --------
__device__ float g_lo[(size_t)NWIN * SEQT * EMB];      // bilstm output, 268MB
__device__ float g_y1[(size_t)NWIN * SEQT * 384];      // q|k|v, 805MB
__device__ float g_pooled[(size_t)NWIN * EMB];         // 8MB
__device__ float g_seq[(size_t)256 * 8192];            // 8MB
__device__ float g_wf[128 * 128];                      // fused proj_w@out_w
__device__ float g_bf[128];                            // fused bias

__device__ __forceinline__ float sigmf(float x) { return 1.f / (1.f + __expf(-x)); }

__device__ __forceinline__ float warp_reduce(float v) {
    #pragma unroll
    for (int off = 16; off > 0; off >>= 1) v += __shfl_xor_sync(0xffffffffu, v, off);
    return v;
}

// ================= 1. BiLSTM (fwd+bwd fused, one window per block) =================
__global__ __launch_bounds__(512) void lstm_kernel(
    const float* __restrict__ x,
    const float* __restrict__ wihf, const float* __restrict__ whhf,
    const float* __restrict__ bihf, const float* __restrict__ bhhf,
    const float* __restrict__ wihb, const float* __restrict__ whhb,
    const float* __restrict__ bihb, const float* __restrict__ bhhb)
{
    int n   = blockIdx.x;
    int tid = threadIdx.x;
    int dir = tid >> 8;     // 0=fwd warps, 1=bwd warps (no intra-warp divergence)
    int g   = tid & 255;    // gate element

    __shared__ float xs[SEQT * FEATN];
    __shared__ float h_sh[2][HID];
    __shared__ float g_sh[2][GATES];

    const float* wih = dir ? wihb : wihf;
    const float* whh = dir ? whhb : whhf;
    const float* bih = dir ? bihb : bihf;
    const float* bhh = dir ? bhhb : bhhf;

    for (int i = tid; i < SEQT * FEATN; i += 512) xs[i] = x[(size_t)n * 512 + i];

    float wi[FEATN];
    #pragma unroll
    for (int f = 0; f < FEATN; f++) wi[f] = wih[g * FEATN + f];
    float wh[HID];
    #pragma unroll
    for (int k = 0; k < HID; k++) wh[k] = whh[g * HID + k];
    float bias = bih[g] + bhh[g];

    if (g < HID) h_sh[dir][g] = 0.f;
    float c = 0.f;
    __syncthreads();

    for (int s = 0; s < SEQT; s++) {
        int t = dir ? (31 - s) : s;
        float acc = bias;
        #pragma unroll
        for (int f = 0; f < FEATN; f++) acc += xs[t * FEATN + f] * wi[f];
        #pragma unroll
        for (int k = 0; k < HID; k++) acc += h_sh[dir][k] * wh[k];
        g_sh[dir][g] = acc;
        __syncthreads();
        if (g < HID) {
            float ig = sigmf(g_sh[dir][g]);
            float fg = sigmf(g_sh[dir][HID + g]);
            float gg = tanhf(g_sh[dir][2 * HID + g]);
            float og = sigmf(g_sh[dir][3 * HID + g]);
            c = fg * c + ig * gg;
            float h = og * tanhf(c);
            h_sh[dir][g] = h;
            g_lo[((size_t)n * SEQT + t) * EMB + dir * HID + g] = h;
        }
        __syncthreads();
    }
}

// ============ 1b. Fuse out_w/proj_w: Wf = proj_w@out_w, bf = proj_w@out_b+proj_b ===
__global__ __launch_bounds__(128) void fuse_kernel(
    const float* __restrict__ out_w, const float* __restrict__ out_b,
    const float* __restrict__ proj_w, const float* __restrict__ proj_b)
{
    int i = blockIdx.x;     // output row
    int c = threadIdx.x;    // output col
    float acc = 0.f;
    #pragma unroll 8
    for (int j = 0; j < 128; j++) acc += proj_w[i * 128 + j] * out_w[j * 128 + c];
    g_wf[i * 128 + c] = acc;
    if (c == 0) {
        float s = proj_b[i];
        for (int j = 0; j < 128; j++) s += proj_w[i * 128 + j] * out_b[j];
        g_bf[i] = s;
    }
}

// ================= 2. QKV GEMM: Y1[524288,384] = LO[524288,128] @ W^T + b ==========
// 128x128 tile, BK=16, 256 threads, 8x8 microtile
__global__ __launch_bounds__(256) void qkv_gemm(const float* __restrict__ W,
                                                const float* __restrict__ bias)
{
    __shared__ float As[16][132];
    __shared__ float Bs[16][132];
    int m0 = blockIdx.y * 128;
    int n0 = blockIdx.x * 128;
    int tid = threadIdx.x;
    int tx = tid & 15, ty = tid >> 4;

    int lr = tid >> 1;            // 0..127 row within tile
    int lc = (tid & 1) * 8;       // 0 or 8: k-offset within BK

    float acc[8][8];
    #pragma unroll
    for (int i = 0; i < 8; i++)
        #pragma unroll
        for (int j = 0; j < 8; j++) acc[i][j] = 0.f;

    for (int kt = 0; kt < 128; kt += 16) {
        __syncthreads();
        float4 a0 = *(const float4*)&g_lo[(size_t)(m0 + lr) * 128 + kt + lc];
        float4 a1 = *(const float4*)&g_lo[(size_t)(m0 + lr) * 128 + kt + lc + 4];
        float4 b0 = *(const float4*)&W[(size_t)(n0 + lr) * 128 + kt + lc];
        float4 b1 = *(const float4*)&W[(size_t)(n0 + lr) * 128 + kt + lc + 4];
        As[lc + 0][lr] = a0.x; As[lc + 1][lr] = a0.y; As[lc + 2][lr] = a0.z; As[lc + 3][lr] = a0.w;
        As[lc + 4][lr] = a1.x; As[lc + 5][lr] = a1.y; As[lc + 6][lr] = a1.z; As[lc + 7][lr] = a1.w;
        Bs[lc + 0][lr] = b0.x; Bs[lc + 1][lr] = b0.y; Bs[lc + 2][lr] = b0.z; Bs[lc + 3][lr] = b0.w;
        Bs[lc + 4][lr] = b1.x; Bs[lc + 5][lr] = b1.y; Bs[lc + 6][lr] = b1.z; Bs[lc + 7][lr] = b1.w;
        __syncthreads();
        #pragma unroll
        for (int k = 0; k < 16; k++) {
            float a[8], b[8];
            *(float4*)&a[0] = *(const float4*)&As[k][ty * 8];
            *(float4*)&a[4] = *(const float4*)&As[k][ty * 8 + 4];
            *(float4*)&b[0] = *(const float4*)&Bs[k][tx * 8];
            *(float4*)&b[4] = *(const float4*)&Bs[k][tx * 8 + 4];
            #pragma unroll
            for (int i = 0; i < 8; i++)
                #pragma unroll
                for (int j = 0; j < 8; j++) acc[i][j] += a[i] * b[j];
        }
    }
    #pragma unroll
    for (int i = 0; i < 8; i++) {
        int m = m0 + ty * 8 + i;
        #pragma unroll
        for (int j = 0; j < 8; j++) {
            int nn = n0 + tx * 8 + j;
            g_y1[(size_t)m * 384 + nn] = acc[i][j] + bias[nn];
        }
    }
}

// ===== 3. Self-attn + fused out/proj + mean-pool (mean-commute trick) ==============
__global__ __launch_bounds__(128) void attn_kernel()
{
    int n = blockIdx.x;
    int tid = threadIdx.x;
    int wid = tid >> 5, lane = tid & 31;
    __shared__ float k_sh[SEQT * EMB];
    __shared__ float v_sh[SEQT * EMB];
    __shared__ float abar[EMB];     // [h*32 + k]: mean_t softmax weights
    __shared__ float oav[EMB];

    const float* y = g_y1 + (size_t)n * SEQT * 384;
    for (int i = tid; i < SEQT * EMB; i += 128) {
        int t = i >> 7, cc = i & 127;
        k_sh[i] = y[t * 384 + 128 + cc];
        v_sh[i] = y[t * 384 + 256 + cc];
    }
    abar[tid] = 0.f;
    __syncthreads();

    int h = wid, t = lane;          // one (head, query-token) row per thread
    float q[32];
    #pragma unroll
    for (int d = 0; d < 32; d++) q[d] = y[t * 384 + h * 32 + d];

    float s[32];
    float mx = -1e30f;
    #pragma unroll
    for (int kk = 0; kk < 32; kk++) {
        float a = 0.f;
        #pragma unroll
        for (int d = 0; d < 32; d++) a += q[d] * k_sh[kk * EMB + h * 32 + d];
        a *= 0.1767766953f;         // 1/sqrt(32)
        s[kk] = a;
        mx = fmaxf(mx, a);
    }
    float sum = 0.f;
    #pragma unroll
    for (int kk = 0; kk < 32; kk++) { float e = __expf(s[kk] - mx); s[kk] = e; sum += e; }
    float inv = 1.f / (sum * 32.f); // softmax + mean over t folded
    #pragma unroll
    for (int k0 = 0; k0 < 32; k0++) {
        int kk = (k0 + t) & 31;     // stagger lanes -> conflict-free smem atomics
        atomicAdd(&abar[h * 32 + kk], s[kk] * inv);
    }
    __syncthreads();

    // mean attention output channel c = tid
    float o = 0.f;
    #pragma unroll
    for (int kk = 0; kk < 32; kk++) o += abar[(tid >> 5) * 32 + kk] * v_sh[kk * EMB + tid];
    oav[tid] = o;
    __syncthreads();

    // fused projection: pooled = Wf @ oav + bf   (warp-per-row, coalesced)
    #pragma unroll 4
    for (int r = 0; r < 32; r++) {
        int row = wid * 32 + r;
        const float* wr = g_wf + row * 128;
        float acc = wr[lane] * oav[lane] + wr[lane + 32] * oav[lane + 32]
                  + wr[lane + 64] * oav[lane + 64] + wr[lane + 96] * oav[lane + 96];
        acc = warp_reduce(acc);
        if (lane == 0) g_pooled[(size_t)n * EMB + row] = acc + g_bf[row];
    }
}

// ================= 4. Cross-attention (q-len 1, <=4 neighbors) + LayerNorm =========
__global__ __launch_bounds__(128) void cross_kernel(
    const float* __restrict__ ca_in_w, const float* __restrict__ ca_in_b,
    const float* __restrict__ ca_out_w, const float* __restrict__ ca_out_b,
    const float* __restrict__ lng, const float* __restrict__ lnb)
{
    int ci = blockIdx.x >> 8;     // weights reused across consecutive blocks
    int b  = blockIdx.x & 255;
    int tid = threadIdx.x;
    int wid = tid >> 5, lane = tid & 31;

    int left  = ci - 2 > 0 ? ci - 2 : 0;
    int right = ci + 3 < 64 ? ci + 3 : 64;
    int idx[4]; int nbr = 0;
    for (int i = left; i < right; i++) if (i != ci) idx[nbr++] = i;

    __shared__ float cen[128], ctx[4][128];
    __shared__ float q_sh[128], k_sh2[4][128], v_sh2[4][128];
    __shared__ float o_sh[128], sc_sh[16], a_w[16], r_sh[128], stats[2];

    cen[tid] = g_pooled[((size_t)b * 64 + ci) * 128 + tid];
    #pragma unroll
    for (int j = 0; j < 4; j++)
        ctx[j][tid] = (j < nbr) ? g_pooled[((size_t)b * 64 + idx[j]) * 128 + tid] : 0.f;
    __syncthreads();

    const float* Wbase = ca_in_w + (size_t)ci * 384 * 128;
    const float* bbase = ca_in_b + ci * 384;

    // --- Q rows (warp-per-row, coalesced weight loads) ---
    for (int r = 0; r < 32; r++) {
        int row = wid * 32 + r;
        const float* wr = Wbase + (size_t)row * 128;
        float acc = wr[lane] * cen[lane] + wr[lane + 32] * cen[lane + 32]
                  + wr[lane + 64] * cen[lane + 64] + wr[lane + 96] * cen[lane + 96];
        acc = warp_reduce(acc);
        if (lane == 0) q_sh[row] = acc + bbase[row];
    }
    // --- K rows (4 neighbor outputs per row) ---
    for (int r = 0; r < 32; r++) {
        int row = wid * 32 + r;
        const float* wr = Wbase + (size_t)(128 + row) * 128;
        float w0 = wr[lane], w1 = wr[lane + 32], w2 = wr[lane + 64], w3 = wr[lane + 96];
        float a0 = w0 * ctx[0][lane] + w1 * ctx[0][lane + 32] + w2 * ctx[0][lane + 64] + w3 * ctx[0][lane + 96];
        float a1 = w0 * ctx[1][lane] + w1 * ctx[1][lane + 32] + w2 * ctx[1][lane + 64] + w3 * ctx[1][lane + 96];
        float a2 = w0 * ctx[2][lane] + w1 * ctx[2][lane + 32] + w2 * ctx[2][lane + 64] + w3 * ctx[2][lane + 96];
        float a3 = w0 * ctx[3][lane] + w1 * ctx[3][lane + 32] + w2 * ctx[3][lane + 64] + w3 * ctx[3][lane + 96];
        a0 = warp_reduce(a0); a1 = warp_reduce(a1);
        a2 = warp_reduce(a2); a3 = warp_reduce(a3);
        if (lane == 0) {
            float bb = bbase[128 + row];
            k_sh2[0][row] = a0 + bb; k_sh2[1][row] = a1 + bb;
            k_sh2[2][row] = a2 + bb; k_sh2[3][row] = a3 + bb;
        }
    }
    // --- V rows ---
    for (int r = 0; r < 32; r++) {
        int row = wid * 32 + r;
        const float* wr = Wbase + (size_t)(256 + row) * 128;
        float w0 = wr[lane], w1 = wr[lane + 32], w2 = wr[lane + 64], w3 = wr[lane + 96];
        float a0 = w0 * ctx[0][lane] + w1 * ctx[0][lane + 32] + w2 * ctx[0][lane + 64] + w3 * ctx[0][lane + 96];
        float a1 = w0 * ctx[1][lane] + w1 * ctx[1][lane + 32] + w2 * ctx[1][lane + 64] + w3 * ctx[1][lane + 96];
        float a2 = w0 * ctx[2][lane] + w1 * ctx[2][lane + 32] + w2 * ctx[2][lane + 64] + w3 * ctx[2][lane + 96];
        float a3 = w0 * ctx[3][lane] + w1 * ctx[3][lane + 32] + w2 * ctx[3][lane + 64] + w3 * ctx[3][lane + 96];
        a0 = warp_reduce(a0); a1 = warp_reduce(a1);
        a2 = warp_reduce(a2); a3 = warp_reduce(a3);
        if (lane == 0) {
            float bb = bbase[256 + row];
            v_sh2[0][row] = a0 + bb; v_sh2[1][row] = a1 + bb;
            v_sh2[2][row] = a2 + bb; v_sh2[3][row] = a3 + bb;
        }
    }
    __syncthreads();

    // --- scores + softmax (4 heads x <=4 neighbors) ---
    if (tid < 16) {
        int h = tid >> 2, j = tid & 3;
        float sv = 0.f;
        if (j < nbr) {
            #pragma unroll
            for (int d = 0; d < 32; d++) sv += q_sh[h * 32 + d] * k_sh2[j][h * 32 + d];
            sv *= 0.1767766953f;
        }
        sc_sh[tid] = sv;
    }
    __syncthreads();
    if (tid < 4) {
        float mx = -1e30f;
        for (int j = 0; j < nbr; j++) mx = fmaxf(mx, sc_sh[tid * 4 + j]);
        float e[4]; float sum = 0.f;
        for (int j = 0; j < nbr; j++) { e[j] = __expf(sc_sh[tid * 4 + j] - mx); sum += e[j]; }
        #pragma unroll
        for (int j = 0; j < 4; j++) a_w[tid * 4 + j] = (j < nbr) ? e[j] / sum : 0.f;
    }
    __syncthreads();

    {
        int h = tid >> 5;
        float o = 0.f;
        #pragma unroll
        for (int j = 0; j < 4; j++) o += a_w[h * 4 + j] * v_sh2[j][tid];
        o_sh[tid] = o;
    }
    __syncthreads();

    // --- out-proj (warp-per-row, coalesced) + residual ---
    for (int r = 0; r < 32; r++) {
        int row = wid * 32 + r;
        const float* wr = ca_out_w + (size_t)ci * 16384 + (size_t)row * 128;
        float acc = wr[lane] * o_sh[lane] + wr[lane + 32] * o_sh[lane + 32]
                  + wr[lane + 64] * o_sh[lane + 64] + wr[lane + 96] * o_sh[lane + 96];
        acc = warp_reduce(acc);
        if (lane == 0) r_sh[row] = acc + ca_out_b[ci * 128 + row] + cen[row];
    }
    __syncthreads();

    // --- LayerNorm ---
    if (tid < 32) {
        float p = r_sh[tid] + r_sh[tid + 32] + r_sh[tid + 64] + r_sh[tid + 96];
        p = warp_reduce(p);
        if (tid == 0) stats[0] = p * (1.f / 128.f);
    }
    __syncthreads();
    float m = stats[0];
    if (tid < 32) {
        float d0 = r_sh[tid] - m, d1 = r_sh[tid + 32] - m;
        float d2 = r_sh[tid + 64] - m, d3 = r_sh[tid + 96] - m;
        float p = d0 * d0 + d1 * d1 + d2 * d2 + d3 * d3;
        p = warp_reduce(p);
        if (tid == 0) stats[1] = p * (1.f / 128.f);
    }
    __syncthreads();
    float yv = (r_sh[tid] - m) * rsqrtf(stats[1] + 1e-5f) * lng[ci * 128 + tid] + lnb[ci * 128 + tid];
    g_seq[(size_t)b * 8192 + ci * 128 + tid] = yv;
}

// ================= 5. Final MLP: relu(seq@fd1^T+b) @ fd2^T + b =====================
__global__ __launch_bounds__(256) void mlp_kernel(
    const float* __restrict__ fd1_w, const float* __restrict__ fd1_b,
    const float* __restrict__ fd2_w, const float* __restrict__ fd2_b,
    float* __restrict__ out)
{
    int b = blockIdx.x;
    int tid = threadIdx.x;
    __shared__ float s_sh[8192];
    __shared__ float h1[64];
    for (int i = tid; i < 8192; i += 256) s_sh[i] = g_seq[(size_t)b * 8192 + i];
    __syncthreads();

    int w = tid >> 5, l = tid & 31;
    for (int j = w; j < 64; j += 8) {
        float acc = 0.f;
        const float* row = fd1_w + (size_t)j * 8192;
        for (int c = l; c < 8192; c += 32) acc += row[c] * s_sh[c];
        acc = warp_reduce(acc);
        if (l == 0) h1[j] = fmaxf(acc + fd1_b[j], 0.f);
    }
    __syncthreads();
    if (tid < 5) {
        float o = fd2_b[tid];
        #pragma unroll
        for (int j = 0; j < 64; j++) o += fd2_w[tid * 64 + j] * h1[j];
        out[b * 5 + tid] = o;
    }
}

// =================================== launch ========================================
extern "C" void kernel_launch(void* const* d_in, const int* in_sizes, int n_in,
                              void* d_out, int out_size)
{
    const float* x        = (const float*)d_in[0];
    const float* wihf     = (const float*)d_in[1];
    const float* whhf     = (const float*)d_in[2];
    const float* bihf     = (const float*)d_in[3];
    const float* bhhf     = (const float*)d_in[4];
    const float* wihb     = (const float*)d_in[5];
    const float* whhb     = (const float*)d_in[6];
    const float* bihb     = (const float*)d_in[7];
    const float* bhhb     = (const float*)d_in[8];
    const float* sa_in_w  = (const float*)d_in[9];
    const float* sa_in_b  = (const float*)d_in[10];
    const float* sa_out_w = (const float*)d_in[11];
    const float* sa_out_b = (const float*)d_in[12];
    const float* proj_w   = (const float*)d_in[13];
    const float* proj_b   = (const float*)d_in[14];
    const float* ca_in_w  = (const float*)d_in[15];
    const float* ca_in_b  = (const float*)d_in[16];
    const float* ca_out_w = (const float*)d_in[17];
    const float* ca_out_b = (const float*)d_in[18];
    const float* ln_g     = (const float*)d_in[19];
    const float* ln_b     = (const float*)d_in[20];
    const float* fd1_w    = (const float*)d_in[21];
    const float* fd1_b    = (const float*)d_in[22];
    const float* fd2_w    = (const float*)d_in[23];
    const float* fd2_b    = (const float*)d_in[24];

    lstm_kernel<<<NWIN, 512>>>(x, wihf, whhf, bihf, bhhf, wihb, whhb, bihb, bhhb);

    fuse_kernel<<<128, 128>>>(sa_out_w, sa_out_b, proj_w, proj_b);

    dim3 g2(3, 4096);   // N tiles x M tiles; x-fastest keeps A-tiles hot in L2
    qkv_gemm<<<g2, 256>>>(sa_in_w, sa_in_b);

    attn_kernel<<<NWIN, 128>>>();

    cross_kernel<<<NWIN, 128>>>(ca_in_w, ca_in_b, ca_out_w, ca_out_b, ln_g, ln_b);

    mlp_kernel<<<256, 256>>>(fd1_w, fd1_b, fd2_w, fd2_b, (float*)d_out);
}

// round 9
// speedup vs baseline: 1.6351x; 1.0433x over previous
#include <cuda_runtime.h>

#define NWIN 16384      // B*NW = 256*64 windows
#define SEQT 32         // WIN
#define FEATN 16
#define HID 64
#define GATES 256       // 4*HID
#define EMB 128

typedef unsigned long long u64;

// -------- scratch (device globals: allocation-free rule) --------
__device__ float g_lo[(size_t)NWIN * SEQT * EMB];      // bilstm output, 268MB
__device__ float g_y1[(size_t)NWIN * SEQT * 384];      // q|k|v, 805MB
__device__ float g_pooled[(size_t)NWIN * EMB];         // 8MB
__device__ float g_seq[(size_t)256 * 8192];            // 8MB
__device__ float g_wf[128 * 128];                      // fused proj_w@out_w
__device__ float g_bf[128];                            // fused bias

__device__ __forceinline__ float sigmf(float x) { return 1.f / (1.f + __expf(-x)); }

__device__ __forceinline__ float warp_reduce(float v) {
    #pragma unroll
    for (int off = 16; off > 0; off >>= 1) v += __shfl_xor_sync(0xffffffffu, v, off);
    return v;
}

// ---- packed fp32x2 helpers (Blackwell FFMA2 path; ptxas never emits it itself) ----
__device__ __forceinline__ u64 pk(float lo, float hi) {
    u64 r; asm("mov.b64 %0, {%1, %2};" : "=l"(r) : "f"(lo), "f"(hi)); return r;
}
__device__ __forceinline__ void upk(u64 v, float& lo, float& hi) {
    asm("mov.b64 {%0, %1}, %2;" : "=f"(lo), "=f"(hi) : "l"(v));
}
__device__ __forceinline__ u64 fma2(u64 a, u64 b, u64 c) {
    u64 d; asm("fma.rn.f32x2 %0, %1, %2, %3;" : "=l"(d) : "l"(a), "l"(b), "l"(c)); return d;
}
__device__ __forceinline__ u64 add2(u64 a, u64 b) {
    u64 d; asm("add.rn.f32x2 %0, %1, %2;" : "=l"(d) : "l"(a), "l"(b)); return d;
}

// ============ 1. BiLSTM: 256 thr/block, each thread owns gate pair (g, g+128) ======
// fp32x2 FFMA2 throughout; h stored duplicated (h,h) in smem so no per-use packing.
__global__ __launch_bounds__(256) void lstm_kernel(
    const float* __restrict__ x,
    const float* __restrict__ wihf, const float* __restrict__ whhf,
    const float* __restrict__ bihf, const float* __restrict__ bhhf,
    const float* __restrict__ wihb, const float* __restrict__ whhb,
    const float* __restrict__ bihb, const float* __restrict__ bhhb)
{
    int n   = blockIdx.x;
    int tid = threadIdx.x;
    int dir = tid >> 7;     // 0=fwd, 1=bwd (warp-aligned split)
    int g2  = tid & 127;    // thread owns gates (g2, g2+128) -> (i,gg) or (f,o)

    __shared__ __align__(16) u64 xs2[SEQT * FEATN];   // (x,x) duplicated pairs
    __shared__ __align__(16) u64 h_sh[2][HID];        // (h,h) duplicated pairs
    __shared__ u64 g2sh[2][128];                      // raw gate pairs

    const float* wih = dir ? wihb : wihf;
    const float* whh = dir ? whhb : whhf;
    const float* bih = dir ? bihb : bihf;
    const float* bhh = dir ? bhhb : bhhf;

    for (int i = tid; i < SEQT * FEATN; i += 256) {
        float v = x[(size_t)n * 512 + i];
        xs2[i] = pk(v, v);
    }

    u64 wi2[FEATN];
    #pragma unroll
    for (int f = 0; f < FEATN; f++)
        wi2[f] = pk(wih[g2 * FEATN + f], wih[(g2 + 128) * FEATN + f]);
    u64 wh2[HID];
    #pragma unroll
    for (int k = 0; k < HID; k++)
        wh2[k] = pk(whh[g2 * HID + k], whh[(g2 + 128) * HID + k]);
    u64 bias2 = pk(bih[g2] + bhh[g2], bih[g2 + 128] + bhh[g2 + 128]);

    if (g2 < HID) h_sh[dir][g2] = 0ull;
    float c = 0.f;
    __syncthreads();

    for (int s = 0; s < SEQT; s++) {
        int t = dir ? (31 - s) : s;
        u64 a0 = bias2, a1 = 0ull, a2 = 0ull, a3 = 0ull;
        const ulonglong2* xp = (const ulonglong2*)&xs2[t * FEATN];
        #pragma unroll
        for (int f2 = 0; f2 < 8; f2 += 2) {
            ulonglong2 x0 = xp[f2], x1 = xp[f2 + 1];
            a0 = fma2(x0.x, wi2[2 * f2 + 0], a0);
            a1 = fma2(x0.y, wi2[2 * f2 + 1], a1);
            a2 = fma2(x1.x, wi2[2 * f2 + 2], a2);
            a3 = fma2(x1.y, wi2[2 * f2 + 3], a3);
        }
        const ulonglong2* hp = (const ulonglong2*)h_sh[dir];
        #pragma unroll
        for (int k2 = 0; k2 < 32; k2 += 2) {
            ulonglong2 h0 = hp[k2], h1 = hp[k2 + 1];
            a0 = fma2(h0.x, wh2[2 * k2 + 0], a0);
            a1 = fma2(h0.y, wh2[2 * k2 + 1], a1);
            a2 = fma2(h1.x, wh2[2 * k2 + 2], a2);
            a3 = fma2(h1.y, wh2[2 * k2 + 3], a3);
        }
        g2sh[dir][g2] = add2(add2(a0, a1), add2(a2, a3));
        __syncthreads();
        if (g2 < HID) {
            float iv, gv, fv, ov;
            upk(g2sh[dir][g2], iv, gv);          // gates (g2, g2+128) = (i, gg)
            upk(g2sh[dir][g2 + 64], fv, ov);     // gates (g2+64, g2+192) = (f, o)
            iv = sigmf(iv); fv = sigmf(fv);
            gv = tanhf(gv); ov = sigmf(ov);
            c = fv * c + iv * gv;
            float h = ov * tanhf(c);
            h_sh[dir][g2] = pk(h, h);
            g_lo[((size_t)n * SEQT + t) * EMB + dir * HID + g2] = h;
        }
        __syncthreads();
    }
}

// ============ 1b. Fuse out_w/proj_w: Wf = proj_w@out_w, bf = proj_w@out_b+proj_b ===
__global__ __launch_bounds__(128) void fuse_kernel(
    const float* __restrict__ out_w, const float* __restrict__ out_b,
    const float* __restrict__ proj_w, const float* __restrict__ proj_b)
{
    int i = blockIdx.x;     // output row
    int c = threadIdx.x;    // output col
    float acc = 0.f;
    #pragma unroll 8
    for (int j = 0; j < 128; j++) acc += proj_w[i * 128 + j] * out_w[j * 128 + c];
    g_wf[i * 128 + c] = acc;
    if (c == 0) {
        float s = proj_b[i];
        for (int j = 0; j < 128; j++) s += proj_w[i * 128 + j] * out_b[j];
        g_bf[i] = s;
    }
}

// ================= 2. QKV GEMM: Y1[524288,384] = LO[524288,128] @ W^T + b ==========
// 128x128 tile, BK=16, 256 threads, 8x8 microtile with f32x2 accumulation
__global__ __launch_bounds__(256) void qkv_gemm(const float* __restrict__ W,
                                                const float* __restrict__ bias)
{
    __shared__ float As[16][132];
    __shared__ float Bs[16][132];
    int m0 = blockIdx.y * 128;
    int n0 = blockIdx.x * 128;
    int tid = threadIdx.x;
    int tx = tid & 15, ty = tid >> 4;

    int lr = tid >> 1;            // 0..127 row within tile
    int lc = (tid & 1) * 8;       // 0 or 8: k-offset within BK

    u64 acc2[8][4];
    #pragma unroll
    for (int i = 0; i < 8; i++)
        #pragma unroll
        for (int j = 0; j < 4; j++) acc2[i][j] = 0ull;

    for (int kt = 0; kt < 128; kt += 16) {
        __syncthreads();
        float4 a0 = *(const float4*)&g_lo[(size_t)(m0 + lr) * 128 + kt + lc];
        float4 a1 = *(const float4*)&g_lo[(size_t)(m0 + lr) * 128 + kt + lc + 4];
        float4 b0 = *(const float4*)&W[(size_t)(n0 + lr) * 128 + kt + lc];
        float4 b1 = *(const float4*)&W[(size_t)(n0 + lr) * 128 + kt + lc + 4];
        As[lc + 0][lr] = a0.x; As[lc + 1][lr] = a0.y; As[lc + 2][lr] = a0.z; As[lc + 3][lr] = a0.w;
        As[lc + 4][lr] = a1.x; As[lc + 5][lr] = a1.y; As[lc + 6][lr] = a1.z; As[lc + 7][lr] = a1.w;
        Bs[lc + 0][lr] = b0.x; Bs[lc + 1][lr] = b0.y; Bs[lc + 2][lr] = b0.z; Bs[lc + 3][lr] = b0.w;
        Bs[lc + 4][lr] = b1.x; Bs[lc + 5][lr] = b1.y; Bs[lc + 6][lr] = b1.z; Bs[lc + 7][lr] = b1.w;
        __syncthreads();
        #pragma unroll
        for (int k = 0; k < 16; k++) {
            float a[8];
            *(float4*)&a[0] = *(const float4*)&As[k][ty * 8];
            *(float4*)&a[4] = *(const float4*)&As[k][ty * 8 + 4];
            u64 b2[4];
            {
                const u64* bp = (const u64*)&Bs[k][tx * 8];
                b2[0] = bp[0]; b2[1] = bp[1]; b2[2] = bp[2]; b2[3] = bp[3];
            }
            #pragma unroll
            for (int i = 0; i < 8; i++) {
                u64 ap = pk(a[i], a[i]);
                #pragma unroll
                for (int j = 0; j < 4; j++) acc2[i][j] = fma2(ap, b2[j], acc2[i][j]);
            }
        }
    }
    #pragma unroll
    for (int i = 0; i < 8; i++) {
        int m = m0 + ty * 8 + i;
        #pragma unroll
        for (int j = 0; j < 4; j++) {
            int nn = n0 + tx * 8 + 2 * j;
            float lo, hi;
            upk(acc2[i][j], lo, hi);
            g_y1[(size_t)m * 384 + nn]     = lo + bias[nn];
            g_y1[(size_t)m * 384 + nn + 1] = hi + bias[nn + 1];
        }
    }
}

// ===== 3. Self-attn + fused out/proj + mean-pool (mean-commute trick) ==============
// coalesced QKV staging; score-matrix transpose reduction (no atomics)
__global__ __launch_bounds__(128) void attn_kernel()
{
    int n = blockIdx.x;
    int tid = threadIdx.x;
    int wid = tid >> 5, lane = tid & 31;
    __shared__ float qbuf[32 * 133];     // q staging; later reused as score matrix
    __shared__ float k_sh[SEQT * EMB];
    __shared__ float v_sh[SEQT * EMB];
    __shared__ float abar_sh[EMB];       // [h*32 + k]: mean_t softmax weights
    __shared__ float oav[EMB];

    const float* y = g_y1 + (size_t)n * SEQT * 384;
    // coalesced float4 staging of all q|k|v
    for (int i4 = tid; i4 < 3072; i4 += 128) {
        int t = i4 / 96;                 // 96 float4 per token row
        int c = (i4 - t * 96) * 4;
        float4 v = ((const float4*)y)[i4];
        if (c < 128) {
            float* q = &qbuf[t * 133 + c];
            q[0] = v.x; q[1] = v.y; q[2] = v.z; q[3] = v.w;
        } else if (c < 256) {
            *(float4*)&k_sh[t * 128 + (c - 128)] = v;
        } else {
            *(float4*)&v_sh[t * 128 + (c - 256)] = v;
        }
    }
    __syncthreads();

    int h = wid, t = lane;               // one (head, query-token) row per thread
    float q[32];
    #pragma unroll
    for (int d = 0; d < 32; d++) q[d] = qbuf[t * 133 + h * 32 + d];  // pitch 133: conflict-free
    __syncthreads();                     // qbuf now dead -> reuse as score matrix

    float s[32];
    float mx = -1e30f;
    #pragma unroll
    for (int kk = 0; kk < 32; kk++) {
        float a = 0.f;
        #pragma unroll
        for (int d = 0; d < 32; d++) a += q[d] * k_sh[kk * EMB + h * 32 + d];
        a *= 0.1767766953f;              // 1/sqrt(32)
        s[kk] = a;
        mx = fmaxf(mx, a);
    }
    float sum = 0.f;
    #pragma unroll
    for (int kk = 0; kk < 32; kk++) { float e = __expf(s[kk] - mx); s[kk] = e; sum += e; }
    float inv = 1.f / (sum * 32.f);      // softmax + mean over t folded
    // transposed store: s_sh[h][kk][t], pitch 33 -> conflict-free both ways
    float* s_sh = qbuf;
    #pragma unroll
    for (int kk = 0; kk < 32; kk++) s_sh[h * 1056 + kk * 33 + t] = s[kk] * inv;
    __syncthreads();

    // column reduction over t: thread (h=wid, kk=lane)
    {
        float ab = 0.f;
        #pragma unroll
        for (int tt = 0; tt < 32; tt++) ab += s_sh[wid * 1056 + lane * 33 + tt];
        abar_sh[wid * 32 + lane] = ab;
    }
    __syncthreads();

    // mean attention output channel c = tid
    float o = 0.f;
    #pragma unroll
    for (int kk = 0; kk < 32; kk++) o += abar_sh[(tid >> 5) * 32 + kk] * v_sh[kk * EMB + tid];
    oav[tid] = o;
    __syncthreads();

    // fused projection: pooled = Wf @ oav + bf   (warp-per-row, coalesced)
    #pragma unroll 4
    for (int r = 0; r < 32; r++) {
        int row = wid * 32 + r;
        const float* wr = g_wf + row * 128;
        float acc = wr[lane] * oav[lane] + wr[lane + 32] * oav[lane + 32]
                  + wr[lane + 64] * oav[lane + 64] + wr[lane + 96] * oav[lane + 96];
        acc = warp_reduce(acc);
        if (lane == 0) g_pooled[(size_t)n * EMB + row] = acc + g_bf[row];
    }
}

// ================= 4. Cross-attention (q-len 1, <=4 neighbors) + LayerNorm =========
__global__ __launch_bounds__(128) void cross_kernel(
    const float* __restrict__ ca_in_w, const float* __restrict__ ca_in_b,
    const float* __restrict__ ca_out_w, const float* __restrict__ ca_out_b,
    const float* __restrict__ lng, const float* __restrict__ lnb)
{
    int ci = blockIdx.x >> 8;     // weights reused across consecutive blocks
    int b  = blockIdx.x & 255;
    int tid = threadIdx.x;
    int wid = tid >> 5, lane = tid & 31;

    int left  = ci - 2 > 0 ? ci - 2 : 0;
    int right = ci + 3 < 64 ? ci + 3 : 64;
    int idx[4]; int nbr = 0;
    for (int i = left; i < right; i++) if (i != ci) idx[nbr++] = i;

    __shared__ float cen[128], ctx[4][128];
    __shared__ float q_sh[128], k_sh2[4][128], v_sh2[4][128];
    __shared__ float o_sh[128], sc_sh[16], a_w[16], r_sh[128], stats[2];

    cen[tid] = g_pooled[((size_t)b * 64 + ci) * 128 + tid];
    #pragma unroll
    for (int j = 0; j < 4; j++)
        ctx[j][tid] = (j < nbr) ? g_pooled[((size_t)b * 64 + idx[j]) * 128 + tid] : 0.f;
    __syncthreads();

    const float* Wbase = ca_in_w + (size_t)ci * 384 * 128;
    const float* bbase = ca_in_b + ci * 384;

    // --- Q rows (warp-per-row, coalesced weight loads) ---
    for (int r = 0; r < 32; r++) {
        int row = wid * 32 + r;
        const float* wr = Wbase + (size_t)row * 128;
        float acc = wr[lane] * cen[lane] + wr[lane + 32] * cen[lane + 32]
                  + wr[lane + 64] * cen[lane + 64] + wr[lane + 96] * cen[lane + 96];
        acc = warp_reduce(acc);
        if (lane == 0) q_sh[row] = acc + bbase[row];
    }
    // --- K rows (4 neighbor outputs per row) ---
    for (int r = 0; r < 32; r++) {
        int row = wid * 32 + r;
        const float* wr = Wbase + (size_t)(128 + row) * 128;
        float w0 = wr[lane], w1 = wr[lane + 32], w2 = wr[lane + 64], w3 = wr[lane + 96];
        float a0 = w0 * ctx[0][lane] + w1 * ctx[0][lane + 32] + w2 * ctx[0][lane + 64] + w3 * ctx[0][lane + 96];
        float a1 = w0 * ctx[1][lane] + w1 * ctx[1][lane + 32] + w2 * ctx[1][lane + 64] + w3 * ctx[1][lane + 96];
        float a2 = w0 * ctx[2][lane] + w1 * ctx[2][lane + 32] + w2 * ctx[2][lane + 64] + w3 * ctx[2][lane + 96];
        float a3 = w0 * ctx[3][lane] + w1 * ctx[3][lane + 32] + w2 * ctx[3][lane + 64] + w3 * ctx[3][lane + 96];
        a0 = warp_reduce(a0); a1 = warp_reduce(a1);
        a2 = warp_reduce(a2); a3 = warp_reduce(a3);
        if (lane == 0) {
            float bb = bbase[128 + row];
            k_sh2[0][row] = a0 + bb; k_sh2[1][row] = a1 + bb;
            k_sh2[2][row] = a2 + bb; k_sh2[3][row] = a3 + bb;
        }
    }
    // --- V rows ---
    for (int r = 0; r < 32; r++) {
        int row = wid * 32 + r;
        const float* wr = Wbase + (size_t)(256 + row) * 128;
        float w0 = wr[lane], w1 = wr[lane + 32], w2 = wr[lane + 64], w3 = wr[lane + 96];
        float a0 = w0 * ctx[0][lane] + w1 * ctx[0][lane + 32] + w2 * ctx[0][lane + 64] + w3 * ctx[0][lane + 96];
        float a1 = w0 * ctx[1][lane] + w1 * ctx[1][lane + 32] + w2 * ctx[1][lane + 64] + w3 * ctx[1][lane + 96];
        float a2 = w0 * ctx[2][lane] + w1 * ctx[2][lane + 32] + w2 * ctx[2][lane + 64] + w3 * ctx[2][lane + 96];
        float a3 = w0 * ctx[3][lane] + w1 * ctx[3][lane + 32] + w2 * ctx[3][lane + 64] + w3 * ctx[3][lane + 96];
        a0 = warp_reduce(a0); a1 = warp_reduce(a1);
        a2 = warp_reduce(a2); a3 = warp_reduce(a3);
        if (lane == 0) {
            float bb = bbase[256 + row];
            v_sh2[0][row] = a0 + bb; v_sh2[1][row] = a1 + bb;
            v_sh2[2][row] = a2 + bb; v_sh2[3][row] = a3 + bb;
        }
    }
    __syncthreads();

    // --- scores + softmax (4 heads x <=4 neighbors) ---
    if (tid < 16) {
        int h = tid >> 2, j = tid & 3;
        float sv = 0.f;
        if (j < nbr) {
            #pragma unroll
            for (int d = 0; d < 32; d++) sv += q_sh[h * 32 + d] * k_sh2[j][h * 32 + d];
            sv *= 0.1767766953f;
        }
        sc_sh[tid] = sv;
    }
    __syncthreads();
    if (tid < 4) {
        float mx = -1e30f;
        for (int j = 0; j < nbr; j++) mx = fmaxf(mx, sc_sh[tid * 4 + j]);
        float e[4]; float sum = 0.f;
        for (int j = 0; j < nbr; j++) { e[j] = __expf(sc_sh[tid * 4 + j] - mx); sum += e[j]; }
        #pragma unroll
        for (int j = 0; j < 4; j++) a_w[tid * 4 + j] = (j < nbr) ? e[j] / sum : 0.f;
    }
    __syncthreads();

    {
        int h = tid >> 5;
        float o = 0.f;
        #pragma unroll
        for (int j = 0; j < 4; j++) o += a_w[h * 4 + j] * v_sh2[j][tid];
        o_sh[tid] = o;
    }
    __syncthreads();

    // --- out-proj (warp-per-row, coalesced) + residual ---
    for (int r = 0; r < 32; r++) {
        int row = wid * 32 + r;
        const float* wr = ca_out_w + (size_t)ci * 16384 + (size_t)row * 128;
        float acc = wr[lane] * o_sh[lane] + wr[lane + 32] * o_sh[lane + 32]
                  + wr[lane + 64] * o_sh[lane + 64] + wr[lane + 96] * o_sh[lane + 96];
        acc = warp_reduce(acc);
        if (lane == 0) r_sh[row] = acc + ca_out_b[ci * 128 + row] + cen[row];
    }
    __syncthreads();

    // --- LayerNorm ---
    if (tid < 32) {
        float p = r_sh[tid] + r_sh[tid + 32] + r_sh[tid + 64] + r_sh[tid + 96];
        p = warp_reduce(p);
        if (tid == 0) stats[0] = p * (1.f / 128.f);
    }
    __syncthreads();
    float m = stats[0];
    if (tid < 32) {
        float d0 = r_sh[tid] - m, d1 = r_sh[tid + 32] - m;
        float d2 = r_sh[tid + 64] - m, d3 = r_sh[tid + 96] - m;
        float p = d0 * d0 + d1 * d1 + d2 * d2 + d3 * d3;
        p = warp_reduce(p);
        if (tid == 0) stats[1] = p * (1.f / 128.f);
    }
    __syncthreads();
    float yv = (r_sh[tid] - m) * rsqrtf(stats[1] + 1e-5f) * lng[ci * 128 + tid] + lnb[ci * 128 + tid];
    g_seq[(size_t)b * 8192 + ci * 128 + tid] = yv;
}

// ================= 5. Final MLP: relu(seq@fd1^T+b) @ fd2^T + b =====================
__global__ __launch_bounds__(256) void mlp_kernel(
    const float* __restrict__ fd1_w, const float* __restrict__ fd1_b,
    const float* __restrict__ fd2_w, const float* __restrict__ fd2_b,
    float* __restrict__ out)
{
    int b = blockIdx.x;
    int tid = threadIdx.x;
    __shared__ float s_sh[8192];
    __shared__ float h1[64];
    for (int i = tid; i < 8192; i += 256) s_sh[i] = g_seq[(size_t)b * 8192 + i];
    __syncthreads();

    int w = tid >> 5, l = tid & 31;
    for (int j = w; j < 64; j += 8) {
        float acc = 0.f;
        const float* row = fd1_w + (size_t)j * 8192;
        for (int c = l; c < 8192; c += 32) acc += row[c] * s_sh[c];
        acc = warp_reduce(acc);
        if (l == 0) h1[j] = fmaxf(acc + fd1_b[j], 0.f);
    }
    __syncthreads();
    if (tid < 5) {
        float o = fd2_b[tid];
        #pragma unroll
        for (int j = 0; j < 64; j++) o += fd2_w[tid * 64 + j] * h1[j];
        out[b * 5 + tid] = o;
    }
}

// =================================== launch ========================================
extern "C" void kernel_launch(void* const* d_in, const int* in_sizes, int n_in,
                              void* d_out, int out_size)
{
    const float* x        = (const float*)d_in[0];
    const float* wihf     = (const float*)d_in[1];
    const float* whhf     = (const float*)d_in[2];
    const float* bihf     = (const float*)d_in[3];
    const float* bhhf     = (const float*)d_in[4];
    const float* wihb     = (const float*)d_in[5];
    const float* whhb     = (const float*)d_in[6];
    const float* bihb     = (const float*)d_in[7];
    const float* bhhb     = (const float*)d_in[8];
    const float* sa_in_w  = (const float*)d_in[9];
    const float* sa_in_b  = (const float*)d_in[10];
    const float* sa_out_w = (const float*)d_in[11];
    const float* sa_out_b = (const float*)d_in[12];
    const float* proj_w   = (const float*)d_in[13];
    const float* proj_b   = (const float*)d_in[14];
    const float* ca_in_w  = (const float*)d_in[15];
    const float* ca_in_b  = (const float*)d_in[16];
    const float* ca_out_w = (const float*)d_in[17];
    const float* ca_out_b = (const float*)d_in[18];
    const float* ln_g     = (const float*)d_in[19];
    const float* ln_b     = (const float*)d_in[20];
    const float* fd1_w    = (const float*)d_in[21];
    const float* fd1_b    = (const float*)d_in[22];
    const float* fd2_w    = (const float*)d_in[23];
    const float* fd2_b    = (const float*)d_in[24];

    lstm_kernel<<<NWIN, 256>>>(x, wihf, whhf, bihf, bhhf, wihb, whhb, bihb, bhhb);

    fuse_kernel<<<128, 128>>>(sa_out_w, sa_out_b, proj_w, proj_b);

    dim3 g2(3, 4096);   // N tiles x M tiles; x-fastest keeps A-tiles hot in L2
    qkv_gemm<<<g2, 256>>>(sa_in_w, sa_in_b);

    attn_kernel<<<NWIN, 128>>>();

    cross_kernel<<<NWIN, 128>>>(ca_in_w, ca_in_b, ca_out_w, ca_out_b, ln_g, ln_b);

    mlp_kernel<<<256, 256>>>(fd1_w, fd1_b, fd2_w, fd2_b, (float*)d_out);
}

// round 11
// speedup vs baseline: 2.0734x; 1.2680x over previous
#include <cuda_runtime.h>

#define NWIN 16384      // B*NW = 256*64 windows
#define SEQT 32         // WIN
#define FEATN 16
#define HID 64
#define GATES 256       // 4*HID
#define EMB 128

typedef unsigned long long u64;

// -------- scratch (device globals: allocation-free rule) --------
__device__ float g_lo[(size_t)NWIN * SEQT * EMB];      // bilstm output, 268MB
__device__ float g_y1[(size_t)NWIN * SEQT * 384];      // q|k|v, 805MB
__device__ float g_pooled[(size_t)NWIN * EMB];         // 8MB
__device__ float g_seq[(size_t)256 * 8192];            // 8MB
__device__ float g_wf[128 * 128];                      // fused proj_w@out_w
__device__ float g_bf[128];                            // fused bias
__device__ u64   g_wpack[2 * 80 * 128];                // [dir][row][g2] packed lstm weights
__device__ u64   g_bias2[2 * 128];                     // packed lstm biases

__device__ __forceinline__ float sigmf(float x) { return 1.f / (1.f + __expf(-x)); }

__device__ __forceinline__ float warp_reduce(float v) {
    #pragma unroll
    for (int off = 16; off > 0; off >>= 1) v += __shfl_xor_sync(0xffffffffu, v, off);
    return v;
}

// ---- packed fp32x2 helpers (Blackwell FFMA2 path; ptxas never emits it itself) ----
__device__ __forceinline__ u64 pk(float lo, float hi) {
    u64 r; asm("mov.b64 %0, {%1, %2};" : "=l"(r) : "f"(lo), "f"(hi)); return r;
}
__device__ __forceinline__ void upk(u64 v, float& lo, float& hi) {
    asm("mov.b64 {%0, %1}, %2;" : "=f"(lo), "=f"(hi) : "l"(v));
}
__device__ __forceinline__ u64 fma2(u64 a, u64 b, u64 c) {
    u64 d; asm("fma.rn.f32x2 %0, %1, %2, %3;" : "=l"(d) : "l"(a), "l"(b), "l"(c)); return d;
}
__device__ __forceinline__ u64 add2(u64 a, u64 b) {
    u64 d; asm("add.rn.f32x2 %0, %1, %2;" : "=l"(d) : "l"(a), "l"(b)); return d;
}
__device__ __forceinline__ void bar_sync(int id, int nthr) {
    asm volatile("bar.sync %0, %1;" :: "r"(id), "r"(nthr) : "memory");
}

// ======== 0. Pack LSTM weights: transposed so lstm loads are coalesced =============
// g_wpack[dir][r][g2]:  r<64 -> whh pair (whh[g2*64+r], whh[(g2+128)*64+r])
//                       r>=64 -> wih pair for f=r-64
__global__ __launch_bounds__(128) void pack_kernel(
    const float* __restrict__ wihf, const float* __restrict__ whhf,
    const float* __restrict__ bihf, const float* __restrict__ bhhf,
    const float* __restrict__ wihb, const float* __restrict__ whhb,
    const float* __restrict__ bihb, const float* __restrict__ bhhb)
{
    int r   = blockIdx.x;     // 0..79
    int dir = blockIdx.y;     // 0..1
    int g2  = threadIdx.x;    // 0..127
    const float* wih = dir ? wihb : wihf;
    const float* whh = dir ? whhb : whhf;
    const float* bih = dir ? bihb : bihf;
    const float* bhh = dir ? bhhb : bhhf;

    u64 v;
    if (r < 64) v = pk(whh[g2 * HID + r], whh[(g2 + 128) * HID + r]);
    else {
        int f = r - 64;
        v = pk(wih[g2 * FEATN + f], wih[(g2 + 128) * FEATN + f]);
    }
    g_wpack[dir * 10240 + r * 128 + g2] = v;
    if (r == 0)
        g_bias2[dir * 128 + g2] = pk(bih[g2] + bhh[g2], bih[g2 + 128] + bhh[g2 + 128]);
}

// ============ 1. BiLSTM: 256 thr/block, each thread owns gate pair (g, g+128) ======
// fp32x2 FFMA2; coalesced packed weight loads; dir-scoped named barriers.
__global__ __launch_bounds__(256) void lstm_kernel(const float* __restrict__ x)
{
    int n   = blockIdx.x;
    int tid = threadIdx.x;
    int dir = tid >> 7;     // 0=fwd, 1=bwd (warp-aligned split)
    int g2  = tid & 127;    // thread owns gates (g2, g2+128) -> (i,gg) or (f,o)

    __shared__ __align__(16) u64 xs2[SEQT * FEATN];   // (x,x) duplicated pairs
    __shared__ __align__(16) u64 h_sh[2][HID];        // (h,h) duplicated pairs
    __shared__ u64 g2sh[2][128];                      // raw gate pairs

    for (int i = tid; i < SEQT * FEATN; i += 256) {
        float v = x[(size_t)n * 512 + i];
        xs2[i] = pk(v, v);
    }

    // coalesced packed weight loads (warp reads 32 consecutive u64 = 2 wavefronts)
    const u64* wp = g_wpack + dir * 10240;
    u64 wh2[HID];
    #pragma unroll
    for (int k = 0; k < HID; k++) wh2[k] = wp[k * 128 + g2];
    u64 wi2[FEATN];
    #pragma unroll
    for (int f = 0; f < FEATN; f++) wi2[f] = wp[(64 + f) * 128 + g2];
    u64 bias2 = g_bias2[dir * 128 + g2];

    if (g2 < HID) h_sh[dir][g2] = 0ull;
    float c = 0.f;
    __syncthreads();

    for (int s = 0; s < SEQT; s++) {
        int t = dir ? (31 - s) : s;
        u64 a0 = bias2, a1 = 0ull, a2 = 0ull, a3 = 0ull;
        const ulonglong2* xp = (const ulonglong2*)&xs2[t * FEATN];
        #pragma unroll
        for (int f2 = 0; f2 < 8; f2 += 2) {
            ulonglong2 x0 = xp[f2], x1 = xp[f2 + 1];
            a0 = fma2(x0.x, wi2[2 * f2 + 0], a0);
            a1 = fma2(x0.y, wi2[2 * f2 + 1], a1);
            a2 = fma2(x1.x, wi2[2 * f2 + 2], a2);
            a3 = fma2(x1.y, wi2[2 * f2 + 3], a3);
        }
        const ulonglong2* hp = (const ulonglong2*)h_sh[dir];
        #pragma unroll
        for (int k2 = 0; k2 < 32; k2 += 2) {
            ulonglong2 h0 = hp[k2], h1 = hp[k2 + 1];
            a0 = fma2(h0.x, wh2[2 * k2 + 0], a0);
            a1 = fma2(h0.y, wh2[2 * k2 + 1], a1);
            a2 = fma2(h1.x, wh2[2 * k2 + 2], a2);
            a3 = fma2(h1.y, wh2[2 * k2 + 3], a3);
        }
        g2sh[dir][g2] = add2(add2(a0, a1), add2(a2, a3));
        bar_sync(dir + 1, 128);
        if (g2 < HID) {
            float iv, gv, fv, ov;
            upk(g2sh[dir][g2], iv, gv);          // gates (g2, g2+128) = (i, gg)
            upk(g2sh[dir][g2 + 64], fv, ov);     // gates (g2+64, g2+192) = (f, o)
            iv = sigmf(iv); fv = sigmf(fv);
            gv = tanhf(gv); ov = sigmf(ov);
            c = fv * c + iv * gv;
            float h = ov * tanhf(c);
            h_sh[dir][g2] = pk(h, h);
            g_lo[((size_t)n * SEQT + t) * EMB + dir * HID + g2] = h;
        }
        bar_sync(dir + 1, 128);
    }
}

// ============ 1b. Fuse out_w/proj_w: Wf = proj_w@out_w, bf = proj_w@out_b+proj_b ===
__global__ __launch_bounds__(128) void fuse_kernel(
    const float* __restrict__ out_w, const float* __restrict__ out_b,
    const float* __restrict__ proj_w, const float* __restrict__ proj_b)
{
    int i = blockIdx.x;     // output row
    int c = threadIdx.x;    // output col
    float acc = 0.f;
    #pragma unroll 8
    for (int j = 0; j < 128; j++) acc += proj_w[i * 128 + j] * out_w[j * 128 + c];
    g_wf[i * 128 + c] = acc;
    if (c == 0) {
        float s = proj_b[i];
        for (int j = 0; j < 128; j++) s += proj_w[i * 128 + j] * out_b[j];
        g_bf[i] = s;
    }
}

// ================= 2. QKV GEMM: Y1[524288,384] = LO[524288,128] @ W^T + b ==========
// 128x128 tile, BK=16, 256 threads, 8x8 microtile, f32x2 accumulation.
// A tile stored pre-duplicated (a,a) in SMEM -> no packing MOVs in inner loop.
__global__ __launch_bounds__(256) void qkv_gemm(const float* __restrict__ W,
                                                const float* __restrict__ bias)
{
    __shared__ __align__(16) u64 As2[16][130];   // (a,a) pairs, pitch 130 (16B-aligned rows)
    __shared__ float Bs[16][132];
    int m0 = blockIdx.y * 128;
    int n0 = blockIdx.x * 128;
    int tid = threadIdx.x;
    int tx = tid & 15, ty = tid >> 4;

    int lr = tid >> 1;            // 0..127 row within tile
    int lc = (tid & 1) * 8;       // 0 or 8: k-offset within BK

    u64 acc2[8][4];
    #pragma unroll
    for (int i = 0; i < 8; i++)
        #pragma unroll
        for (int j = 0; j < 4; j++) acc2[i][j] = 0ull;

    for (int kt = 0; kt < 128; kt += 16) {
        __syncthreads();
        float4 a0 = *(const float4*)&g_lo[(size_t)(m0 + lr) * 128 + kt + lc];
        float4 a1 = *(const float4*)&g_lo[(size_t)(m0 + lr) * 128 + kt + lc + 4];
        float4 b0 = *(const float4*)&W[(size_t)(n0 + lr) * 128 + kt + lc];
        float4 b1 = *(const float4*)&W[(size_t)(n0 + lr) * 128 + kt + lc + 4];
        As2[lc + 0][lr] = pk(a0.x, a0.x); As2[lc + 1][lr] = pk(a0.y, a0.y);
        As2[lc + 2][lr] = pk(a0.z, a0.z); As2[lc + 3][lr] = pk(a0.w, a0.w);
        As2[lc + 4][lr] = pk(a1.x, a1.x); As2[lc + 5][lr] = pk(a1.y, a1.y);
        As2[lc + 6][lr] = pk(a1.z, a1.z); As2[lc + 7][lr] = pk(a1.w, a1.w);
        Bs[lc + 0][lr] = b0.x; Bs[lc + 1][lr] = b0.y; Bs[lc + 2][lr] = b0.z; Bs[lc + 3][lr] = b0.w;
        Bs[lc + 4][lr] = b1.x; Bs[lc + 5][lr] = b1.y; Bs[lc + 6][lr] = b1.z; Bs[lc + 7][lr] = b1.w;
        __syncthreads();
        #pragma unroll
        for (int k = 0; k < 16; k++) {
            u64 a2[8];
            {
                const ulonglong2* ap = (const ulonglong2*)&As2[k][ty * 8];
                ulonglong2 p0 = ap[0], p1 = ap[1], p2 = ap[2], p3 = ap[3];
                a2[0] = p0.x; a2[1] = p0.y; a2[2] = p1.x; a2[3] = p1.y;
                a2[4] = p2.x; a2[5] = p2.y; a2[6] = p3.x; a2[7] = p3.y;
            }
            u64 b2[4];
            {
                const u64* bp = (const u64*)&Bs[k][tx * 8];
                b2[0] = bp[0]; b2[1] = bp[1]; b2[2] = bp[2]; b2[3] = bp[3];
            }
            #pragma unroll
            for (int i = 0; i < 8; i++)
                #pragma unroll
                for (int j = 0; j < 4; j++) acc2[i][j] = fma2(a2[i], b2[j], acc2[i][j]);
        }
    }
    #pragma unroll
    for (int i = 0; i < 8; i++) {
        int m = m0 + ty * 8 + i;
        #pragma unroll
        for (int j = 0; j < 4; j++) {
            int nn = n0 + tx * 8 + 2 * j;
            float lo, hi;
            upk(acc2[i][j], lo, hi);
            g_y1[(size_t)m * 384 + nn]     = lo + bias[nn];
            g_y1[(size_t)m * 384 + nn + 1] = hi + bias[nn + 1];
        }
    }
}

// ===== 3. Self-attn + fused out/proj + mean-pool (mean-commute trick) ==============
__global__ __launch_bounds__(128) void attn_kernel()
{
    int n = blockIdx.x;
    int tid = threadIdx.x;
    int wid = tid >> 5, lane = tid & 31;
    __shared__ float qbuf[32 * 133];     // q staging; later reused as score matrix
    __shared__ float k_sh[SEQT * EMB];
    __shared__ float v_sh[SEQT * EMB];
    __shared__ float abar_sh[EMB];       // [h*32 + k]: mean_t softmax weights
    __shared__ float oav[EMB];

    const float* y = g_y1 + (size_t)n * SEQT * 384;
    // coalesced float4 staging of all q|k|v
    for (int i4 = tid; i4 < 3072; i4 += 128) {
        int t = i4 / 96;                 // 96 float4 per token row
        int c = (i4 - t * 96) * 4;
        float4 v = ((const float4*)y)[i4];
        if (c < 128) {
            float* q = &qbuf[t * 133 + c];
            q[0] = v.x; q[1] = v.y; q[2] = v.z; q[3] = v.w;
        } else if (c < 256) {
            *(float4*)&k_sh[t * 128 + (c - 128)] = v;
        } else {
            *(float4*)&v_sh[t * 128 + (c - 256)] = v;
        }
    }
    __syncthreads();

    int h = wid, t = lane;               // one (head, query-token) row per thread
    float q[32];
    #pragma unroll
    for (int d = 0; d < 32; d++) q[d] = qbuf[t * 133 + h * 32 + d];  // pitch 133: conflict-free
    __syncthreads();                     // qbuf now dead -> reuse as score matrix

    float s[32];
    float mx = -1e30f;
    #pragma unroll
    for (int kk = 0; kk < 32; kk++) {
        float a = 0.f;
        #pragma unroll
        for (int d = 0; d < 32; d++) a += q[d] * k_sh[kk * EMB + h * 32 + d];
        a *= 0.1767766953f;              // 1/sqrt(32)
        s[kk] = a;
        mx = fmaxf(mx, a);
    }
    float sum = 0.f;
    #pragma unroll
    for (int kk = 0; kk < 32; kk++) { float e = __expf(s[kk] - mx); s[kk] = e; sum += e; }
    float inv = 1.f / (sum * 32.f);      // softmax + mean over t folded
    // transposed store: s_sh[h][kk][t], pitch 33 -> conflict-free both ways
    float* s_sh = qbuf;
    #pragma unroll
    for (int kk = 0; kk < 32; kk++) s_sh[h * 1056 + kk * 33 + t] = s[kk] * inv;
    __syncthreads();

    // column reduction over t: thread (h=wid, kk=lane)
    {
        float ab = 0.f;
        #pragma unroll
        for (int tt = 0; tt < 32; tt++) ab += s_sh[wid * 1056 + lane * 33 + tt];
        abar_sh[wid * 32 + lane] = ab;
    }
    __syncthreads();

    // mean attention output channel c = tid
    float o = 0.f;
    #pragma unroll
    for (int kk = 0; kk < 32; kk++) o += abar_sh[(tid >> 5) * 32 + kk] * v_sh[kk * EMB + tid];
    oav[tid] = o;
    __syncthreads();

    // fused projection: pooled = Wf @ oav + bf   (warp-per-row, coalesced)
    #pragma unroll 4
    for (int r = 0; r < 32; r++) {
        int row = wid * 32 + r;
        const float* wr = g_wf + row * 128;
        float acc = wr[lane] * oav[lane] + wr[lane + 32] * oav[lane + 32]
                  + wr[lane + 64] * oav[lane + 64] + wr[lane + 96] * oav[lane + 96];
        acc = warp_reduce(acc);
        if (lane == 0) g_pooled[(size_t)n * EMB + row] = acc + g_bf[row];
    }
}

// ================= 4. Cross-attention (q-len 1, <=4 neighbors) + LayerNorm =========
__global__ __launch_bounds__(128) void cross_kernel(
    const float* __restrict__ ca_in_w, const float* __restrict__ ca_in_b,
    const float* __restrict__ ca_out_w, const float* __restrict__ ca_out_b,
    const float* __restrict__ lng, const float* __restrict__ lnb)
{
    int ci = blockIdx.x >> 8;     // weights reused across consecutive blocks
    int b  = blockIdx.x & 255;
    int tid = threadIdx.x;
    int wid = tid >> 5, lane = tid & 31;

    int left  = ci - 2 > 0 ? ci - 2 : 0;
    int right = ci + 3 < 64 ? ci + 3 : 64;
    int idx[4]; int nbr = 0;
    for (int i = left; i < right; i++) if (i != ci) idx[nbr++] = i;

    __shared__ float cen[128], ctx[4][128];
    __shared__ float q_sh[128], k_sh2[4][128], v_sh2[4][128];
    __shared__ float o_sh[128], sc_sh[16], a_w[16], r_sh[128], stats[2];

    cen[tid] = g_pooled[((size_t)b * 64 + ci) * 128 + tid];
    #pragma unroll
    for (int j = 0; j < 4; j++)
        ctx[j][tid] = (j < nbr) ? g_pooled[((size_t)b * 64 + idx[j]) * 128 + tid] : 0.f;
    __syncthreads();

    const float* Wbase = ca_in_w + (size_t)ci * 384 * 128;
    const float* bbase = ca_in_b + ci * 384;

    // --- Q rows (warp-per-row, coalesced weight loads) ---
    for (int r = 0; r < 32; r++) {
        int row = wid * 32 + r;
        const float* wr = Wbase + (size_t)row * 128;
        float acc = wr[lane] * cen[lane] + wr[lane + 32] * cen[lane + 32]
                  + wr[lane + 64] * cen[lane + 64] + wr[lane + 96] * cen[lane + 96];
        acc = warp_reduce(acc);
        if (lane == 0) q_sh[row] = acc + bbase[row];
    }
    // --- K rows (4 neighbor outputs per row) ---
    for (int r = 0; r < 32; r++) {
        int row = wid * 32 + r;
        const float* wr = Wbase + (size_t)(128 + row) * 128;
        float w0 = wr[lane], w1 = wr[lane + 32], w2 = wr[lane + 64], w3 = wr[lane + 96];
        float a0 = w0 * ctx[0][lane] + w1 * ctx[0][lane + 32] + w2 * ctx[0][lane + 64] + w3 * ctx[0][lane + 96];
        float a1 = w0 * ctx[1][lane] + w1 * ctx[1][lane + 32] + w2 * ctx[1][lane + 64] + w3 * ctx[1][lane + 96];
        float a2 = w0 * ctx[2][lane] + w1 * ctx[2][lane + 32] + w2 * ctx[2][lane + 64] + w3 * ctx[2][lane + 96];
        float a3 = w0 * ctx[3][lane] + w1 * ctx[3][lane + 32] + w2 * ctx[3][lane + 64] + w3 * ctx[3][lane + 96];
        a0 = warp_reduce(a0); a1 = warp_reduce(a1);
        a2 = warp_reduce(a2); a3 = warp_reduce(a3);
        if (lane == 0) {
            float bb = bbase[128 + row];
            k_sh2[0][row] = a0 + bb; k_sh2[1][row] = a1 + bb;
            k_sh2[2][row] = a2 + bb; k_sh2[3][row] = a3 + bb;
        }
    }
    // --- V rows ---
    for (int r = 0; r < 32; r++) {
        int row = wid * 32 + r;
        const float* wr = Wbase + (size_t)(256 + row) * 128;
        float w0 = wr[lane], w1 = wr[lane + 32], w2 = wr[lane + 64], w3 = wr[lane + 96];
        float a0 = w0 * ctx[0][lane] + w1 * ctx[0][lane + 32] + w2 * ctx[0][lane + 64] + w3 * ctx[0][lane + 96];
        float a1 = w0 * ctx[1][lane] + w1 * ctx[1][lane + 32] + w2 * ctx[1][lane + 64] + w3 * ctx[1][lane + 96];
        float a2 = w0 * ctx[2][lane] + w1 * ctx[2][lane + 32] + w2 * ctx[2][lane + 64] + w3 * ctx[2][lane + 96];
        float a3 = w0 * ctx[3][lane] + w1 * ctx[3][lane + 32] + w2 * ctx[3][lane + 64] + w3 * ctx[3][lane + 96];
        a0 = warp_reduce(a0); a1 = warp_reduce(a1);
        a2 = warp_reduce(a2); a3 = warp_reduce(a3);
        if (lane == 0) {
            float bb = bbase[256 + row];
            v_sh2[0][row] = a0 + bb; v_sh2[1][row] = a1 + bb;
            v_sh2[2][row] = a2 + bb; v_sh2[3][row] = a3 + bb;
        }
    }
    __syncthreads();

    // --- scores + softmax (4 heads x <=4 neighbors) ---
    if (tid < 16) {
        int h = tid >> 2, j = tid & 3;
        float sv = 0.f;
        if (j < nbr) {
            #pragma unroll
            for (int d = 0; d < 32; d++) sv += q_sh[h * 32 + d] * k_sh2[j][h * 32 + d];
            sv *= 0.1767766953f;
        }
        sc_sh[tid] = sv;
    }
    __syncthreads();
    if (tid < 4) {
        float mx = -1e30f;
        for (int j = 0; j < nbr; j++) mx = fmaxf(mx, sc_sh[tid * 4 + j]);
        float e[4]; float sum = 0.f;
        for (int j = 0; j < nbr; j++) { e[j] = __expf(sc_sh[tid * 4 + j] - mx); sum += e[j]; }
        #pragma unroll
        for (int j = 0; j < 4; j++) a_w[tid * 4 + j] = (j < nbr) ? e[j] / sum : 0.f;
    }
    __syncthreads();

    {
        int h = tid >> 5;
        float o = 0.f;
        #pragma unroll
        for (int j = 0; j < 4; j++) o += a_w[h * 4 + j] * v_sh2[j][tid];
        o_sh[tid] = o;
    }
    __syncthreads();

    // --- out-proj (warp-per-row, coalesced) + residual ---
    for (int r = 0; r < 32; r++) {
        int row = wid * 32 + r;
        const float* wr = ca_out_w + (size_t)ci * 16384 + (size_t)row * 128;
        float acc = wr[lane] * o_sh[lane] + wr[lane + 32] * o_sh[lane + 32]
                  + wr[lane + 64] * o_sh[lane + 64] + wr[lane + 96] * o_sh[lane + 96];
        acc = warp_reduce(acc);
        if (lane == 0) r_sh[row] = acc + ca_out_b[ci * 128 + row] + cen[row];
    }
    __syncthreads();

    // --- LayerNorm ---
    if (tid < 32) {
        float p = r_sh[tid] + r_sh[tid + 32] + r_sh[tid + 64] + r_sh[tid + 96];
        p = warp_reduce(p);
        if (tid == 0) stats[0] = p * (1.f / 128.f);
    }
    __syncthreads();
    float m = stats[0];
    if (tid < 32) {
        float d0 = r_sh[tid] - m, d1 = r_sh[tid + 32] - m;
        float d2 = r_sh[tid + 64] - m, d3 = r_sh[tid + 96] - m;
        float p = d0 * d0 + d1 * d1 + d2 * d2 + d3 * d3;
        p = warp_reduce(p);
        if (tid == 0) stats[1] = p * (1.f / 128.f);
    }
    __syncthreads();
    float yv = (r_sh[tid] - m) * rsqrtf(stats[1] + 1e-5f) * lng[ci * 128 + tid] + lnb[ci * 128 + tid];
    g_seq[(size_t)b * 8192 + ci * 128 + tid] = yv;
}

// ================= 5. Final MLP: relu(seq@fd1^T+b) @ fd2^T + b =====================
__global__ __launch_bounds__(256) void mlp_kernel(
    const float* __restrict__ fd1_w, const float* __restrict__ fd1_b,
    const float* __restrict__ fd2_w, const float* __restrict__ fd2_b,
    float* __restrict__ out)
{
    int b = blockIdx.x;
    int tid = threadIdx.x;
    __shared__ float s_sh[8192];
    __shared__ float h1[64];
    for (int i = tid; i < 8192; i += 256) s_sh[i] = g_seq[(size_t)b * 8192 + i];
    __syncthreads();

    int w = tid >> 5, l = tid & 31;
    for (int j = w; j < 64; j += 8) {
        float acc = 0.f;
        const float* row = fd1_w + (size_t)j * 8192;
        for (int c = l; c < 8192; c += 32) acc += row[c] * s_sh[c];
        acc = warp_reduce(acc);
        if (l == 0) h1[j] = fmaxf(acc + fd1_b[j], 0.f);
    }
    __syncthreads();
    if (tid < 5) {
        float o = fd2_b[tid];
        #pragma unroll
        for (int j = 0; j < 64; j++) o += fd2_w[tid * 64 + j] * h1[j];
        out[b * 5 + tid] = o;
    }
}

// =================================== launch ========================================
extern "C" void kernel_launch(void* const* d_in, const int* in_sizes, int n_in,
                              void* d_out, int out_size)
{
    const float* x        = (const float*)d_in[0];
    const float* wihf     = (const float*)d_in[1];
    const float* whhf     = (const float*)d_in[2];
    const float* bihf     = (const float*)d_in[3];
    const float* bhhf     = (const float*)d_in[4];
    const float* wihb     = (const float*)d_in[5];
    const float* whhb     = (const float*)d_in[6];
    const float* bihb     = (const float*)d_in[7];
    const float* bhhb     = (const float*)d_in[8];
    const float* sa_in_w  = (const float*)d_in[9];
    const float* sa_in_b  = (const float*)d_in[10];
    const float* sa_out_w = (const float*)d_in[11];
    const float* sa_out_b = (const float*)d_in[12];
    const float* proj_w   = (const float*)d_in[13];
    const float* proj_b   = (const float*)d_in[14];
    const float* ca_in_w  = (const float*)d_in[15];
    const float* ca_in_b  = (const float*)d_in[16];
    const float* ca_out_w = (const float*)d_in[17];
    const float* ca_out_b = (const float*)d_in[18];
    const float* ln_g     = (const float*)d_in[19];
    const float* ln_b     = (const float*)d_in[20];
    const float* fd1_w    = (const float*)d_in[21];
    const float* fd1_b    = (const float*)d_in[22];
    const float* fd2_w    = (const float*)d_in[23];
    const float* fd2_b    = (const float*)d_in[24];

    dim3 gp(80, 2);
    pack_kernel<<<gp, 128>>>(wihf, whhf, bihf, bhhf, wihb, whhb, bihb, bhhb);

    fuse_kernel<<<128, 128>>>(sa_out_w, sa_out_b, proj_w, proj_b);

    lstm_kernel<<<NWIN, 256>>>(x);

    dim3 g2(3, 4096);   // N tiles x M tiles; x-fastest keeps A-tiles hot in L2
    qkv_gemm<<<g2, 256>>>(sa_in_w, sa_in_b);

    attn_kernel<<<NWIN, 128>>>();

    cross_kernel<<<NWIN, 128>>>(ca_in_w, ca_in_b, ca_out_w, ca_out_b, ln_g, ln_b);

    mlp_kernel<<<256, 256>>>(fd1_w, fd1_b, fd2_w, fd2_b, (float*)d_out);
}

// round 12
// speedup vs baseline: 2.1459x; 1.0350x over previous
#include <cuda_runtime.h>

#define NWIN 16384      // B*NW = 256*64 windows
#define SEQT 32         // WIN
#define FEATN 16
#define HID 64
#define GATES 256       // 4*HID
#define EMB 128

typedef unsigned long long u64;

// -------- scratch (device globals: allocation-free rule) --------
__device__ float g_lo[(size_t)NWIN * SEQT * EMB];      // bilstm output, 268MB
__device__ float g_y1[(size_t)NWIN * SEQT * 384];      // q|k|v, 805MB
__device__ float g_pooled[(size_t)NWIN * EMB];         // 8MB
__device__ float g_seq[(size_t)256 * 8192];            // 8MB
__device__ float g_wf[128 * 128];                      // fused proj_w@out_w
__device__ float g_bf[128];                            // fused bias
__device__ u64   g_wpack[2 * 80 * 128];                // [dir][row][g2] packed lstm weights
__device__ u64   g_bias2[2 * 128];                     // packed lstm biases

__device__ __forceinline__ float sigmf(float x) { return 1.f / (1.f + __expf(-x)); }

__device__ __forceinline__ float warp_reduce(float v) {
    #pragma unroll
    for (int off = 16; off > 0; off >>= 1) v += __shfl_xor_sync(0xffffffffu, v, off);
    return v;
}

// ---- packed fp32x2 helpers (Blackwell FFMA2 path; ptxas never emits it itself) ----
__device__ __forceinline__ u64 pk(float lo, float hi) {
    u64 r; asm("mov.b64 %0, {%1, %2};" : "=l"(r) : "f"(lo), "f"(hi)); return r;
}
__device__ __forceinline__ void upk(u64 v, float& lo, float& hi) {
    asm("mov.b64 {%0, %1}, %2;" : "=f"(lo), "=f"(hi) : "l"(v));
}
__device__ __forceinline__ u64 fma2(u64 a, u64 b, u64 c) {
    u64 d; asm("fma.rn.f32x2 %0, %1, %2, %3;" : "=l"(d) : "l"(a), "l"(b), "l"(c)); return d;
}
__device__ __forceinline__ u64 add2(u64 a, u64 b) {
    u64 d; asm("add.rn.f32x2 %0, %1, %2;" : "=l"(d) : "l"(a), "l"(b)); return d;
}
__device__ __forceinline__ void bar_sync(int id, int nthr) {
    asm volatile("bar.sync %0, %1;" :: "r"(id), "r"(nthr) : "memory");
}

// ======== 0. Pack LSTM weights: transposed so lstm loads are coalesced =============
__global__ __launch_bounds__(128) void pack_kernel(
    const float* __restrict__ wihf, const float* __restrict__ whhf,
    const float* __restrict__ bihf, const float* __restrict__ bhhf,
    const float* __restrict__ wihb, const float* __restrict__ whhb,
    const float* __restrict__ bihb, const float* __restrict__ bhhb)
{
    int r   = blockIdx.x;     // 0..79
    int dir = blockIdx.y;     // 0..1
    int g2  = threadIdx.x;    // 0..127
    const float* wih = dir ? wihb : wihf;
    const float* whh = dir ? whhb : whhf;
    const float* bih = dir ? bihb : bihf;
    const float* bhh = dir ? bhhb : bhhf;

    u64 v;
    if (r < 64) v = pk(whh[g2 * HID + r], whh[(g2 + 128) * HID + r]);
    else {
        int f = r - 64;
        v = pk(wih[g2 * FEATN + f], wih[(g2 + 128) * FEATN + f]);
    }
    g_wpack[dir * 10240 + r * 128 + g2] = v;
    if (r == 0)
        g_bias2[dir * 128 + g2] = pk(bih[g2] + bhh[g2], bih[g2 + 128] + bhh[g2 + 128]);
}

// ============ 1. BiLSTM: 256 thr/block, each thread owns gate pair (g, g+128) ======
__global__ __launch_bounds__(256) void lstm_kernel(const float* __restrict__ x)
{
    int n   = blockIdx.x;
    int tid = threadIdx.x;
    int dir = tid >> 7;     // 0=fwd, 1=bwd (warp-aligned split)
    int g2  = tid & 127;    // thread owns gates (g2, g2+128) -> (i,gg) or (f,o)

    __shared__ __align__(16) u64 xs2[SEQT * FEATN];   // (x,x) duplicated pairs
    __shared__ __align__(16) u64 h_sh[2][HID];        // (h,h) duplicated pairs
    __shared__ u64 g2sh[2][128];                      // raw gate pairs

    for (int i = tid; i < SEQT * FEATN; i += 256) {
        float v = x[(size_t)n * 512 + i];
        xs2[i] = pk(v, v);
    }

    // coalesced packed weight loads (warp reads 32 consecutive u64 = 2 wavefronts)
    const u64* wp = g_wpack + dir * 10240;
    u64 wh2[HID];
    #pragma unroll
    for (int k = 0; k < HID; k++) wh2[k] = wp[k * 128 + g2];
    u64 wi2[FEATN];
    #pragma unroll
    for (int f = 0; f < FEATN; f++) wi2[f] = wp[(64 + f) * 128 + g2];
    u64 bias2 = g_bias2[dir * 128 + g2];

    if (g2 < HID) h_sh[dir][g2] = 0ull;
    float c = 0.f;
    __syncthreads();

    for (int s = 0; s < SEQT; s++) {
        int t = dir ? (31 - s) : s;
        u64 a0 = bias2, a1 = 0ull, a2 = 0ull, a3 = 0ull;
        const ulonglong2* xp = (const ulonglong2*)&xs2[t * FEATN];
        #pragma unroll
        for (int f2 = 0; f2 < 8; f2 += 2) {
            ulonglong2 x0 = xp[f2], x1 = xp[f2 + 1];
            a0 = fma2(x0.x, wi2[2 * f2 + 0], a0);
            a1 = fma2(x0.y, wi2[2 * f2 + 1], a1);
            a2 = fma2(x1.x, wi2[2 * f2 + 2], a2);
            a3 = fma2(x1.y, wi2[2 * f2 + 3], a3);
        }
        const ulonglong2* hp = (const ulonglong2*)h_sh[dir];
        #pragma unroll
        for (int k2 = 0; k2 < 32; k2 += 2) {
            ulonglong2 h0 = hp[k2], h1 = hp[k2 + 1];
            a0 = fma2(h0.x, wh2[2 * k2 + 0], a0);
            a1 = fma2(h0.y, wh2[2 * k2 + 1], a1);
            a2 = fma2(h1.x, wh2[2 * k2 + 2], a2);
            a3 = fma2(h1.y, wh2[2 * k2 + 3], a3);
        }
        g2sh[dir][g2] = add2(add2(a0, a1), add2(a2, a3));
        bar_sync(dir + 1, 128);
        if (g2 < HID) {
            float iv, gv, fv, ov;
            upk(g2sh[dir][g2], iv, gv);          // gates (g2, g2+128) = (i, gg)
            upk(g2sh[dir][g2 + 64], fv, ov);     // gates (g2+64, g2+192) = (f, o)
            iv = sigmf(iv); fv = sigmf(fv);
            gv = tanhf(gv); ov = sigmf(ov);
            c = fv * c + iv * gv;
            float h = ov * tanhf(c);
            h_sh[dir][g2] = pk(h, h);
            g_lo[((size_t)n * SEQT + t) * EMB + dir * HID + g2] = h;
        }
        bar_sync(dir + 1, 128);
    }
}

// ============ 1b. Fuse out_w/proj_w: Wf = proj_w@out_w, bf = proj_w@out_b+proj_b ===
__global__ __launch_bounds__(128) void fuse_kernel(
    const float* __restrict__ out_w, const float* __restrict__ out_b,
    const float* __restrict__ proj_w, const float* __restrict__ proj_b)
{
    int i = blockIdx.x;     // output row
    int c = threadIdx.x;    // output col
    float acc = 0.f;
    #pragma unroll 8
    for (int j = 0; j < 128; j++) acc += proj_w[i * 128 + j] * out_w[j * 128 + c];
    g_wf[i * 128 + c] = acc;
    if (c == 0) {
        float s = proj_b[i];
        for (int j = 0; j < 128; j++) s += proj_w[i * 128 + j] * out_b[j];
        g_bf[i] = s;
    }
}

// ================= 2. QKV GEMM: Y1[524288,384] = LO[524288,128] @ W^T + b ==========
// 128x128 tile, BK=16, 256 threads, 8x8 microtile, f32x2 accumulation.
// NON-duplicated SMEM (4 LDS.128/thread/k); splat packs go to the idle ALU pipe.
__global__ __launch_bounds__(256, 2) void qkv_gemm(const float* __restrict__ W,
                                                   const float* __restrict__ bias)
{
    __shared__ float As[16][132];
    __shared__ float Bs[16][132];
    int m0 = blockIdx.y * 128;
    int n0 = blockIdx.x * 128;
    int tid = threadIdx.x;
    int tx = tid & 15, ty = tid >> 4;

    int lr = tid >> 1;            // 0..127 row within tile
    int lc = (tid & 1) * 8;       // 0 or 8: k-offset within BK

    u64 acc2[8][4];
    #pragma unroll
    for (int i = 0; i < 8; i++)
        #pragma unroll
        for (int j = 0; j < 4; j++) acc2[i][j] = 0ull;

    for (int kt = 0; kt < 128; kt += 16) {
        __syncthreads();
        float4 a0 = *(const float4*)&g_lo[(size_t)(m0 + lr) * 128 + kt + lc];
        float4 a1 = *(const float4*)&g_lo[(size_t)(m0 + lr) * 128 + kt + lc + 4];
        float4 b0 = *(const float4*)&W[(size_t)(n0 + lr) * 128 + kt + lc];
        float4 b1 = *(const float4*)&W[(size_t)(n0 + lr) * 128 + kt + lc + 4];
        As[lc + 0][lr] = a0.x; As[lc + 1][lr] = a0.y; As[lc + 2][lr] = a0.z; As[lc + 3][lr] = a0.w;
        As[lc + 4][lr] = a1.x; As[lc + 5][lr] = a1.y; As[lc + 6][lr] = a1.z; As[lc + 7][lr] = a1.w;
        Bs[lc + 0][lr] = b0.x; Bs[lc + 1][lr] = b0.y; Bs[lc + 2][lr] = b0.z; Bs[lc + 3][lr] = b0.w;
        Bs[lc + 4][lr] = b1.x; Bs[lc + 5][lr] = b1.y; Bs[lc + 6][lr] = b1.z; Bs[lc + 7][lr] = b1.w;
        __syncthreads();
        #pragma unroll
        for (int k = 0; k < 16; k++) {
            float a[8];
            *(float4*)&a[0] = *(const float4*)&As[k][ty * 8];
            *(float4*)&a[4] = *(const float4*)&As[k][ty * 8 + 4];
            u64 b2[4];
            {
                const u64* bp = (const u64*)&Bs[k][tx * 8];
                b2[0] = bp[0]; b2[1] = bp[1]; b2[2] = bp[2]; b2[3] = bp[3];
            }
            #pragma unroll
            for (int i = 0; i < 8; i++) {
                u64 ap = pk(a[i], a[i]);
                #pragma unroll
                for (int j = 0; j < 4; j++) acc2[i][j] = fma2(ap, b2[j], acc2[i][j]);
            }
        }
    }
    #pragma unroll
    for (int i = 0; i < 8; i++) {
        int m = m0 + ty * 8 + i;
        #pragma unroll
        for (int j = 0; j < 4; j++) {
            int nn = n0 + tx * 8 + 2 * j;
            float lo, hi;
            upk(acc2[i][j], lo, hi);
            g_y1[(size_t)m * 384 + nn]     = lo + bias[nn];
            g_y1[(size_t)m * 384 + nn + 1] = hi + bias[nn + 1];
        }
    }
}

// ===== 3. Self-attn + fused out/proj + mean-pool (mean-commute trick) ==============
// f32x2 score path: 8 LDS.128 + 16 FFMA2 per key (was 32 scalar LDS + 32 FMA)
__global__ __launch_bounds__(128) void attn_kernel()
{
    int n = blockIdx.x;
    int tid = threadIdx.x;
    int wid = tid >> 5, lane = tid & 31;
    __shared__ float qbuf[32 * 133];     // q staging; later reused as score matrix
    __shared__ float k_sh[SEQT * EMB];
    __shared__ float v_sh[SEQT * EMB];
    __shared__ float abar_sh[EMB];       // [h*32 + k]: mean_t softmax weights
    __shared__ float oav[EMB];

    const float* y = g_y1 + (size_t)n * SEQT * 384;
    // coalesced float4 staging of all q|k|v
    for (int i4 = tid; i4 < 3072; i4 += 128) {
        int t = i4 / 96;                 // 96 float4 per token row
        int c = (i4 - t * 96) * 4;
        float4 v = ((const float4*)y)[i4];
        if (c < 128) {
            float* q = &qbuf[t * 133 + c];
            q[0] = v.x; q[1] = v.y; q[2] = v.z; q[3] = v.w;
        } else if (c < 256) {
            *(float4*)&k_sh[t * 128 + (c - 128)] = v;
        } else {
            *(float4*)&v_sh[t * 128 + (c - 256)] = v;
        }
    }
    __syncthreads();

    int h = wid, t = lane;               // one (head, query-token) row per thread
    // q as 16 natural f32x2 pairs (pitch-133 reads: conflict-free)
    u64 q2[16];
    #pragma unroll
    for (int d2 = 0; d2 < 16; d2++)
        q2[d2] = pk(qbuf[t * 133 + h * 32 + 2 * d2], qbuf[t * 133 + h * 32 + 2 * d2 + 1]);
    __syncthreads();                     // qbuf now dead -> reuse as score matrix

    float s[32];
    float mx = -1e30f;
    #pragma unroll
    for (int kk = 0; kk < 32; kk++) {
        const ulonglong2* kp2 = (const ulonglong2*)&k_sh[kk * EMB + h * 32];  // 16B aligned, broadcast
        u64 accA = 0ull, accB = 0ull;
        #pragma unroll
        for (int d4 = 0; d4 < 8; d4++) {
            ulonglong2 kv = kp2[d4];
            accA = fma2(kv.x, q2[2 * d4], accA);
            accB = fma2(kv.y, q2[2 * d4 + 1], accB);
        }
        float lo, hi; upk(add2(accA, accB), lo, hi);
        float a = (lo + hi) * 0.1767766953f;   // 1/sqrt(32)
        s[kk] = a;
        mx = fmaxf(mx, a);
    }
    float sum = 0.f;
    #pragma unroll
    for (int kk = 0; kk < 32; kk++) { float e = __expf(s[kk] - mx); s[kk] = e; sum += e; }
    float inv = 1.f / (sum * 32.f);      // softmax + mean over t folded
    // transposed store: s_sh[h][kk][t], pitch 33 -> conflict-free both ways
    float* s_sh = qbuf;
    #pragma unroll
    for (int kk = 0; kk < 32; kk++) s_sh[h * 1056 + kk * 33 + t] = s[kk] * inv;
    __syncthreads();

    // column reduction over t: thread (h=wid, kk=lane)
    {
        float ab = 0.f;
        #pragma unroll
        for (int tt = 0; tt < 32; tt++) ab += s_sh[wid * 1056 + lane * 33 + tt];
        abar_sh[wid * 32 + lane] = ab;
    }
    __syncthreads();

    // mean attention output channel c = tid
    float o = 0.f;
    #pragma unroll
    for (int kk = 0; kk < 32; kk++) o += abar_sh[(tid >> 5) * 32 + kk] * v_sh[kk * EMB + tid];
    oav[tid] = o;
    __syncthreads();

    // fused projection: pooled = Wf @ oav + bf   (warp-per-row, coalesced)
    #pragma unroll 4
    for (int r = 0; r < 32; r++) {
        int row = wid * 32 + r;
        const float* wr = g_wf + row * 128;
        float acc = wr[lane] * oav[lane] + wr[lane + 32] * oav[lane + 32]
                  + wr[lane + 64] * oav[lane + 64] + wr[lane + 96] * oav[lane + 96];
        acc = warp_reduce(acc);
        if (lane == 0) g_pooled[(size_t)n * EMB + row] = acc + g_bf[row];
    }
}

// ================= 4. Cross-attention (q-len 1, <=4 neighbors) + LayerNorm =========
__global__ __launch_bounds__(128) void cross_kernel(
    const float* __restrict__ ca_in_w, const float* __restrict__ ca_in_b,
    const float* __restrict__ ca_out_w, const float* __restrict__ ca_out_b,
    const float* __restrict__ lng, const float* __restrict__ lnb)
{
    int ci = blockIdx.x >> 8;     // weights reused across consecutive blocks
    int b  = blockIdx.x & 255;
    int tid = threadIdx.x;
    int wid = tid >> 5, lane = tid & 31;

    int left  = ci - 2 > 0 ? ci - 2 : 0;
    int right = ci + 3 < 64 ? ci + 3 : 64;
    int idx[4]; int nbr = 0;
    for (int i = left; i < right; i++) if (i != ci) idx[nbr++] = i;

    __shared__ float cen[128], ctx[4][128];
    __shared__ float q_sh[128], k_sh2[4][128], v_sh2[4][128];
    __shared__ float o_sh[128], sc_sh[16], a_w[16], r_sh[128], stats[2];

    cen[tid] = g_pooled[((size_t)b * 64 + ci) * 128 + tid];
    #pragma unroll
    for (int j = 0; j < 4; j++)
        ctx[j][tid] = (j < nbr) ? g_pooled[((size_t)b * 64 + idx[j]) * 128 + tid] : 0.f;
    __syncthreads();

    const float* Wbase = ca_in_w + (size_t)ci * 384 * 128;
    const float* bbase = ca_in_b + ci * 384;

    // --- Q rows (warp-per-row, coalesced weight loads) ---
    for (int r = 0; r < 32; r++) {
        int row = wid * 32 + r;
        const float* wr = Wbase + (size_t)row * 128;
        float acc = wr[lane] * cen[lane] + wr[lane + 32] * cen[lane + 32]
                  + wr[lane + 64] * cen[lane + 64] + wr[lane + 96] * cen[lane + 96];
        acc = warp_reduce(acc);
        if (lane == 0) q_sh[row] = acc + bbase[row];
    }
    // --- K rows (4 neighbor outputs per row) ---
    for (int r = 0; r < 32; r++) {
        int row = wid * 32 + r;
        const float* wr = Wbase + (size_t)(128 + row) * 128;
        float w0 = wr[lane], w1 = wr[lane + 32], w2 = wr[lane + 64], w3 = wr[lane + 96];
        float a0 = w0 * ctx[0][lane] + w1 * ctx[0][lane + 32] + w2 * ctx[0][lane + 64] + w3 * ctx[0][lane + 96];
        float a1 = w0 * ctx[1][lane] + w1 * ctx[1][lane + 32] + w2 * ctx[1][lane + 64] + w3 * ctx[1][lane + 96];
        float a2 = w0 * ctx[2][lane] + w1 * ctx[2][lane + 32] + w2 * ctx[2][lane + 64] + w3 * ctx[2][lane + 96];
        float a3 = w0 * ctx[3][lane] + w1 * ctx[3][lane + 32] + w2 * ctx[3][lane + 64] + w3 * ctx[3][lane + 96];
        a0 = warp_reduce(a0); a1 = warp_reduce(a1);
        a2 = warp_reduce(a2); a3 = warp_reduce(a3);
        if (lane == 0) {
            float bb = bbase[128 + row];
            k_sh2[0][row] = a0 + bb; k_sh2[1][row] = a1 + bb;
            k_sh2[2][row] = a2 + bb; k_sh2[3][row] = a3 + bb;
        }
    }
    // --- V rows ---
    for (int r = 0; r < 32; r++) {
        int row = wid * 32 + r;
        const float* wr = Wbase + (size_t)(256 + row) * 128;
        float w0 = wr[lane], w1 = wr[lane + 32], w2 = wr[lane + 64], w3 = wr[lane + 96];
        float a0 = w0 * ctx[0][lane] + w1 * ctx[0][lane + 32] + w2 * ctx[0][lane + 64] + w3 * ctx[0][lane + 96];
        float a1 = w0 * ctx[1][lane] + w1 * ctx[1][lane + 32] + w2 * ctx[1][lane + 64] + w3 * ctx[1][lane + 96];
        float a2 = w0 * ctx[2][lane] + w1 * ctx[2][lane + 32] + w2 * ctx[2][lane + 64] + w3 * ctx[2][lane + 96];
        float a3 = w0 * ctx[3][lane] + w1 * ctx[3][lane + 32] + w2 * ctx[3][lane + 64] + w3 * ctx[3][lane + 96];
        a0 = warp_reduce(a0); a1 = warp_reduce(a1);
        a2 = warp_reduce(a2); a3 = warp_reduce(a3);
        if (lane == 0) {
            float bb = bbase[256 + row];
            v_sh2[0][row] = a0 + bb; v_sh2[1][row] = a1 + bb;
            v_sh2[2][row] = a2 + bb; v_sh2[3][row] = a3 + bb;
        }
    }
    __syncthreads();

    // --- scores + softmax (4 heads x <=4 neighbors) ---
    if (tid < 16) {
        int h = tid >> 2, j = tid & 3;
        float sv = 0.f;
        if (j < nbr) {
            #pragma unroll
            for (int d = 0; d < 32; d++) sv += q_sh[h * 32 + d] * k_sh2[j][h * 32 + d];
            sv *= 0.1767766953f;
        }
        sc_sh[tid] = sv;
    }
    __syncthreads();
    if (tid < 4) {
        float mx = -1e30f;
        for (int j = 0; j < nbr; j++) mx = fmaxf(mx, sc_sh[tid * 4 + j]);
        float e[4]; float sum = 0.f;
        for (int j = 0; j < nbr; j++) { e[j] = __expf(sc_sh[tid * 4 + j] - mx); sum += e[j]; }
        #pragma unroll
        for (int j = 0; j < 4; j++) a_w[tid * 4 + j] = (j < nbr) ? e[j] / sum : 0.f;
    }
    __syncthreads();

    {
        int h = tid >> 5;
        float o = 0.f;
        #pragma unroll
        for (int j = 0; j < 4; j++) o += a_w[h * 4 + j] * v_sh2[j][tid];
        o_sh[tid] = o;
    }
    __syncthreads();

    // --- out-proj (warp-per-row, coalesced) + residual ---
    for (int r = 0; r < 32; r++) {
        int row = wid * 32 + r;
        const float* wr = ca_out_w + (size_t)ci * 16384 + (size_t)row * 128;
        float acc = wr[lane] * o_sh[lane] + wr[lane + 32] * o_sh[lane + 32]
                  + wr[lane + 64] * o_sh[lane + 64] + wr[lane + 96] * o_sh[lane + 96];
        acc = warp_reduce(acc);
        if (lane == 0) r_sh[row] = acc + ca_out_b[ci * 128 + row] + cen[row];
    }
    __syncthreads();

    // --- LayerNorm ---
    if (tid < 32) {
        float p = r_sh[tid] + r_sh[tid + 32] + r_sh[tid + 64] + r_sh[tid + 96];
        p = warp_reduce(p);
        if (tid == 0) stats[0] = p * (1.f / 128.f);
    }
    __syncthreads();
    float m = stats[0];
    if (tid < 32) {
        float d0 = r_sh[tid] - m, d1 = r_sh[tid + 32] - m;
        float d2 = r_sh[tid + 64] - m, d3 = r_sh[tid + 96] - m;
        float p = d0 * d0 + d1 * d1 + d2 * d2 + d3 * d3;
        p = warp_reduce(p);
        if (tid == 0) stats[1] = p * (1.f / 128.f);
    }
    __syncthreads();
    float yv = (r_sh[tid] - m) * rsqrtf(stats[1] + 1e-5f) * lng[ci * 128 + tid] + lnb[ci * 128 + tid];
    g_seq[(size_t)b * 8192 + ci * 128 + tid] = yv;
}

// ================= 5. Final MLP: relu(seq@fd1^T+b) @ fd2^T + b =====================
__global__ __launch_bounds__(256) void mlp_kernel(
    const float* __restrict__ fd1_w, const float* __restrict__ fd1_b,
    const float* __restrict__ fd2_w, const float* __restrict__ fd2_b,
    float* __restrict__ out)
{
    int b = blockIdx.x;
    int tid = threadIdx.x;
    __shared__ float s_sh[8192];
    __shared__ float h1[64];
    for (int i = tid; i < 8192; i += 256) s_sh[i] = g_seq[(size_t)b * 8192 + i];
    __syncthreads();

    int w = tid >> 5, l = tid & 31;
    for (int j = w; j < 64; j += 8) {
        float acc = 0.f;
        const float* row = fd1_w + (size_t)j * 8192;
        for (int c = l; c < 8192; c += 32) acc += row[c] * s_sh[c];
        acc = warp_reduce(acc);
        if (l == 0) h1[j] = fmaxf(acc + fd1_b[j], 0.f);
    }
    __syncthreads();
    if (tid < 5) {
        float o = fd2_b[tid];
        #pragma unroll
        for (int j = 0; j < 64; j++) o += fd2_w[tid * 64 + j] * h1[j];
        out[b * 5 + tid] = o;
    }
}

// =================================== launch ========================================
extern "C" void kernel_launch(void* const* d_in, const int* in_sizes, int n_in,
                              void* d_out, int out_size)
{
    const float* x        = (const float*)d_in[0];
    const float* wihf     = (const float*)d_in[1];
    const float* whhf     = (const float*)d_in[2];
    const float* bihf     = (const float*)d_in[3];
    const float* bhhf     = (const float*)d_in[4];
    const float* wihb     = (const float*)d_in[5];
    const float* whhb     = (const float*)d_in[6];
    const float* bihb     = (const float*)d_in[7];
    const float* bhhb     = (const float*)d_in[8];
    const float* sa_in_w  = (const float*)d_in[9];
    const float* sa_in_b  = (const float*)d_in[10];
    const float* sa_out_w = (const float*)d_in[11];
    const float* sa_out_b = (const float*)d_in[12];
    const float* proj_w   = (const float*)d_in[13];
    const float* proj_b   = (const float*)d_in[14];
    const float* ca_in_w  = (const float*)d_in[15];
    const float* ca_in_b  = (const float*)d_in[16];
    const float* ca_out_w = (const float*)d_in[17];
    const float* ca_out_b = (const float*)d_in[18];
    const float* ln_g     = (const float*)d_in[19];
    const float* ln_b     = (const float*)d_in[20];
    const float* fd1_w    = (const float*)d_in[21];
    const float* fd1_b    = (const float*)d_in[22];
    const float* fd2_w    = (const float*)d_in[23];
    const float* fd2_b    = (const float*)d_in[24];

    dim3 gp(80, 2);
    pack_kernel<<<gp, 128>>>(wihf, whhf, bihf, bhhf, wihb, whhb, bihb, bhhb);

    fuse_kernel<<<128, 128>>>(sa_out_w, sa_out_b, proj_w, proj_b);

    lstm_kernel<<<NWIN, 256>>>(x);

    dim3 g2(3, 4096);   // N tiles x M tiles; x-fastest keeps A-tiles hot in L2
    qkv_gemm<<<g2, 256>>>(sa_in_w, sa_in_b);

    attn_kernel<<<NWIN, 128>>>();

    cross_kernel<<<NWIN, 128>>>(ca_in_w, ca_in_b, ca_out_w, ca_out_b, ln_g, ln_b);

    mlp_kernel<<<256, 256>>>(fd1_w, fd1_b, fd2_w, fd2_b, (float*)d_out);
}

// round 14
// speedup vs baseline: 2.1565x; 1.0049x over previous
#include <cuda_runtime.h>

#define NWIN 16384      // B*NW = 256*64 windows
#define SEQT 32         // WIN
#define FEATN 16
#define HID 64
#define GATES 256       // 4*HID
#define EMB 128

typedef unsigned long long u64;

// -------- scratch (device globals: allocation-free rule) --------
__device__ float g_lo[(size_t)NWIN * SEQT * EMB];      // bilstm output, 268MB
__device__ float g_y1[(size_t)NWIN * SEQT * 384];      // q|k|v, 805MB
__device__ float g_pooled[(size_t)NWIN * EMB];         // 8MB
__device__ float g_seq[(size_t)256 * 8192];            // 8MB
__device__ float g_wf[128 * 128];                      // fused proj_w@out_w
__device__ float g_bf[128];                            // fused bias
__device__ u64   g_wpack[2 * 80 * 128];                // [dir][row][g2] packed lstm weights
__device__ u64   g_bias2[2 * 128];                     // packed lstm biases

__device__ __forceinline__ float sigmf(float x) { return 1.f / (1.f + __expf(-x)); }

__device__ __forceinline__ float warp_reduce(float v) {
    #pragma unroll
    for (int off = 16; off > 0; off >>= 1) v += __shfl_xor_sync(0xffffffffu, v, off);
    return v;
}

// ---- packed fp32x2 helpers (Blackwell FFMA2 path; ptxas never emits it itself) ----
__device__ __forceinline__ u64 pk(float lo, float hi) {
    u64 r; asm("mov.b64 %0, {%1, %2};" : "=l"(r) : "f"(lo), "f"(hi)); return r;
}
__device__ __forceinline__ void upk(u64 v, float& lo, float& hi) {
    asm("mov.b64 {%0, %1}, %2;" : "=f"(lo), "=f"(hi) : "l"(v));
}
__device__ __forceinline__ u64 fma2(u64 a, u64 b, u64 c) {
    u64 d; asm("fma.rn.f32x2 %0, %1, %2, %3;" : "=l"(d) : "l"(a), "l"(b), "l"(c)); return d;
}
__device__ __forceinline__ u64 add2(u64 a, u64 b) {
    u64 d; asm("add.rn.f32x2 %0, %1, %2;" : "=l"(d) : "l"(a), "l"(b)); return d;
}
__device__ __forceinline__ void bar_sync(int id, int nthr) {
    asm volatile("bar.sync %0, %1;" :: "r"(id), "r"(nthr) : "memory");
}

// ======== 0. Pack LSTM weights: transposed so lstm loads are coalesced =============
__global__ __launch_bounds__(128) void pack_kernel(
    const float* __restrict__ wihf, const float* __restrict__ whhf,
    const float* __restrict__ bihf, const float* __restrict__ bhhf,
    const float* __restrict__ wihb, const float* __restrict__ whhb,
    const float* __restrict__ bihb, const float* __restrict__ bhhb)
{
    int r   = blockIdx.x;     // 0..79
    int dir = blockIdx.y;     // 0..1
    int g2  = threadIdx.x;    // 0..127
    const float* wih = dir ? wihb : wihf;
    const float* whh = dir ? whhb : whhf;
    const float* bih = dir ? bihb : bihf;
    const float* bhh = dir ? bhhb : bhhf;

    u64 v;
    if (r < 64) v = pk(whh[g2 * HID + r], whh[(g2 + 128) * HID + r]);
    else {
        int f = r - 64;
        v = pk(wih[g2 * FEATN + f], wih[(g2 + 128) * FEATN + f]);
    }
    g_wpack[dir * 10240 + r * 128 + g2] = v;
    if (r == 0)
        g_bias2[dir * 128 + g2] = pk(bih[g2] + bhh[g2], bih[g2 + 128] + bhh[g2 + 128]);
}

// ============ 1. BiLSTM: 256 thr/block, each thread owns gate pair (g, g+128) ======
__global__ __launch_bounds__(256) void lstm_kernel(const float* __restrict__ x)
{
    int n   = blockIdx.x;
    int tid = threadIdx.x;
    int dir = tid >> 7;     // 0=fwd, 1=bwd (warp-aligned split)
    int g2  = tid & 127;    // thread owns gates (g2, g2+128) -> (i,gg) or (f,o)

    __shared__ __align__(16) u64 xs2[SEQT * FEATN];   // (x,x) duplicated pairs
    __shared__ __align__(16) u64 h_sh[2][HID];        // (h,h) duplicated pairs
    __shared__ u64 g2sh[2][128];                      // raw gate pairs

    for (int i = tid; i < SEQT * FEATN; i += 256) {
        float v = x[(size_t)n * 512 + i];
        xs2[i] = pk(v, v);
    }

    // coalesced packed weight loads (warp reads 32 consecutive u64 = 2 wavefronts)
    const u64* wp = g_wpack + dir * 10240;
    u64 wh2[HID];
    #pragma unroll
    for (int k = 0; k < HID; k++) wh2[k] = wp[k * 128 + g2];
    u64 wi2[FEATN];
    #pragma unroll
    for (int f = 0; f < FEATN; f++) wi2[f] = wp[(64 + f) * 128 + g2];
    u64 bias2 = g_bias2[dir * 128 + g2];

    if (g2 < HID) h_sh[dir][g2] = 0ull;
    float c = 0.f;
    __syncthreads();

    for (int s = 0; s < SEQT; s++) {
        int t = dir ? (31 - s) : s;
        u64 a0 = bias2, a1 = 0ull, a2 = 0ull, a3 = 0ull;
        const ulonglong2* xp = (const ulonglong2*)&xs2[t * FEATN];
        #pragma unroll
        for (int f2 = 0; f2 < 8; f2 += 2) {
            ulonglong2 x0 = xp[f2], x1 = xp[f2 + 1];
            a0 = fma2(x0.x, wi2[2 * f2 + 0], a0);
            a1 = fma2(x0.y, wi2[2 * f2 + 1], a1);
            a2 = fma2(x1.x, wi2[2 * f2 + 2], a2);
            a3 = fma2(x1.y, wi2[2 * f2 + 3], a3);
        }
        const ulonglong2* hp = (const ulonglong2*)h_sh[dir];
        #pragma unroll
        for (int k2 = 0; k2 < 32; k2 += 2) {
            ulonglong2 h0 = hp[k2], h1 = hp[k2 + 1];
            a0 = fma2(h0.x, wh2[2 * k2 + 0], a0);
            a1 = fma2(h0.y, wh2[2 * k2 + 1], a1);
            a2 = fma2(h1.x, wh2[2 * k2 + 2], a2);
            a3 = fma2(h1.y, wh2[2 * k2 + 3], a3);
        }
        g2sh[dir][g2] = add2(add2(a0, a1), add2(a2, a3));
        bar_sync(dir + 1, 128);
        if (g2 < HID) {
            float iv, gv, fv, ov;
            upk(g2sh[dir][g2], iv, gv);          // gates (g2, g2+128) = (i, gg)
            upk(g2sh[dir][g2 + 64], fv, ov);     // gates (g2+64, g2+192) = (f, o)
            iv = sigmf(iv); fv = sigmf(fv);
            gv = tanhf(gv); ov = sigmf(ov);
            c = fv * c + iv * gv;
            float h = ov * tanhf(c);
            h_sh[dir][g2] = pk(h, h);
            g_lo[((size_t)n * SEQT + t) * EMB + dir * HID + g2] = h;
        }
        bar_sync(dir + 1, 128);
    }
}

// ============ 1b. Fuse out_w/proj_w: Wf = proj_w@out_w, bf = proj_w@out_b+proj_b ===
__global__ __launch_bounds__(128) void fuse_kernel(
    const float* __restrict__ out_w, const float* __restrict__ out_b,
    const float* __restrict__ proj_w, const float* __restrict__ proj_b)
{
    int i = blockIdx.x;     // output row
    int c = threadIdx.x;    // output col
    float acc = 0.f;
    #pragma unroll 8
    for (int j = 0; j < 128; j++) acc += proj_w[i * 128 + j] * out_w[j * 128 + c];
    g_wf[i * 128 + c] = acc;
    if (c == 0) {
        float s = proj_b[i];
        for (int j = 0; j < 128; j++) s += proj_w[i * 128 + j] * out_b[j];
        g_bf[i] = s;
    }
}

// ================= 2. QKV GEMM: Y1[524288,384] = LO[524288,128] @ W^T + b ==========
// 128x128 tile, BK=16, 256 threads, 8x8 microtile, f32x2 accumulation.
// 2-stage software pipeline: prefetch next k-tile into regs during compute;
// one __syncthreads per iteration (double-buffered SMEM).
__global__ __launch_bounds__(256, 2) void qkv_gemm(const float* __restrict__ W,
                                                   const float* __restrict__ bias)
{
    __shared__ float As[2][16][132];
    __shared__ float Bs[2][16][132];
    int m0 = blockIdx.y * 128;
    int n0 = blockIdx.x * 128;
    int tid = threadIdx.x;
    int tx = tid & 15, ty = tid >> 4;

    int lr = tid >> 1;            // 0..127 row within tile
    int lc = (tid & 1) * 8;       // 0 or 8: k-offset within BK

    const float* aptr = &g_lo[(size_t)(m0 + lr) * 128 + lc];
    const float* bptr = &W[(size_t)(n0 + lr) * 128 + lc];

    u64 acc2[8][4];
    #pragma unroll
    for (int i = 0; i < 8; i++)
        #pragma unroll
        for (int j = 0; j < 4; j++) acc2[i][j] = 0ull;

    // prologue: load k-tile 0
    float4 ra0 = *(const float4*)(aptr);
    float4 ra1 = *(const float4*)(aptr + 4);
    float4 rb0 = *(const float4*)(bptr);
    float4 rb1 = *(const float4*)(bptr + 4);

    #pragma unroll
    for (int it = 0; it < 8; it++) {
        int buf = it & 1;
        // store staged regs into current buffer
        As[buf][lc + 0][lr] = ra0.x; As[buf][lc + 1][lr] = ra0.y;
        As[buf][lc + 2][lr] = ra0.z; As[buf][lc + 3][lr] = ra0.w;
        As[buf][lc + 4][lr] = ra1.x; As[buf][lc + 5][lr] = ra1.y;
        As[buf][lc + 6][lr] = ra1.z; As[buf][lc + 7][lr] = ra1.w;
        Bs[buf][lc + 0][lr] = rb0.x; Bs[buf][lc + 1][lr] = rb0.y;
        Bs[buf][lc + 2][lr] = rb0.z; Bs[buf][lc + 3][lr] = rb0.w;
        Bs[buf][lc + 4][lr] = rb1.x; Bs[buf][lc + 5][lr] = rb1.y;
        Bs[buf][lc + 6][lr] = rb1.z; Bs[buf][lc + 7][lr] = rb1.w;
        __syncthreads();

        // prefetch next k-tile (overlapped with compute below)
        if (it < 7) {
            int kt = (it + 1) * 16;
            ra0 = *(const float4*)(aptr + kt);
            ra1 = *(const float4*)(aptr + kt + 4);
            rb0 = *(const float4*)(bptr + kt);
            rb1 = *(const float4*)(bptr + kt + 4);
        }

        #pragma unroll
        for (int k = 0; k < 16; k++) {
            float a[8];
            *(float4*)&a[0] = *(const float4*)&As[buf][k][ty * 8];
            *(float4*)&a[4] = *(const float4*)&As[buf][k][ty * 8 + 4];
            u64 b2[4];
            {
                const u64* bp = (const u64*)&Bs[buf][k][tx * 8];
                b2[0] = bp[0]; b2[1] = bp[1]; b2[2] = bp[2]; b2[3] = bp[3];
            }
            #pragma unroll
            for (int i = 0; i < 8; i++) {
                u64 ap = pk(a[i], a[i]);
                #pragma unroll
                for (int j = 0; j < 4; j++) acc2[i][j] = fma2(ap, b2[j], acc2[i][j]);
            }
        }
        __syncthreads();
    }

    #pragma unroll
    for (int i = 0; i < 8; i++) {
        int m = m0 + ty * 8 + i;
        #pragma unroll
        for (int j = 0; j < 4; j++) {
            int nn = n0 + tx * 8 + 2 * j;
            float lo, hi;
            upk(acc2[i][j], lo, hi);
            g_y1[(size_t)m * 384 + nn]     = lo + bias[nn];
            g_y1[(size_t)m * 384 + nn + 1] = hi + bias[nn + 1];
        }
    }
}

// ===== 3. Self-attn + fused out/proj + mean-pool (mean-commute trick) ==============
// f32x2 score path: 8 LDS.128 + 16 FFMA2 per key
__global__ __launch_bounds__(128) void attn_kernel()
{
    int n = blockIdx.x;
    int tid = threadIdx.x;
    int wid = tid >> 5, lane = tid & 31;
    __shared__ float qbuf[32 * 133];     // q staging; later reused as score matrix
    __shared__ float k_sh[SEQT * EMB];
    __shared__ float v_sh[SEQT * EMB];
    __shared__ float abar_sh[EMB];       // [h*32 + k]: mean_t softmax weights
    __shared__ float oav[EMB];

    const float* y = g_y1 + (size_t)n * SEQT * 384;
    // coalesced float4 staging of all q|k|v
    for (int i4 = tid; i4 < 3072; i4 += 128) {
        int t = i4 / 96;                 // 96 float4 per token row
        int c = (i4 - t * 96) * 4;
        float4 v = ((const float4*)y)[i4];
        if (c < 128) {
            float* q = &qbuf[t * 133 + c];
            q[0] = v.x; q[1] = v.y; q[2] = v.z; q[3] = v.w;
        } else if (c < 256) {
            *(float4*)&k_sh[t * 128 + (c - 128)] = v;
        } else {
            *(float4*)&v_sh[t * 128 + (c - 256)] = v;
        }
    }
    __syncthreads();

    int h = wid, t = lane;               // one (head, query-token) row per thread
    // q as 16 natural f32x2 pairs (pitch-133 reads: conflict-free)
    u64 q2[16];
    #pragma unroll
    for (int d2 = 0; d2 < 16; d2++)
        q2[d2] = pk(qbuf[t * 133 + h * 32 + 2 * d2], qbuf[t * 133 + h * 32 + 2 * d2 + 1]);
    __syncthreads();                     // qbuf now dead -> reuse as score matrix

    float s[32];
    float mx = -1e30f;
    #pragma unroll
    for (int kk = 0; kk < 32; kk++) {
        const ulonglong2* kp2 = (const ulonglong2*)&k_sh[kk * EMB + h * 32];  // 16B aligned, broadcast
        u64 accA = 0ull, accB = 0ull;
        #pragma unroll
        for (int d4 = 0; d4 < 8; d4++) {
            ulonglong2 kv = kp2[d4];
            accA = fma2(kv.x, q2[2 * d4], accA);
            accB = fma2(kv.y, q2[2 * d4 + 1], accB);
        }
        float lo, hi; upk(add2(accA, accB), lo, hi);
        float a = (lo + hi) * 0.1767766953f;   // 1/sqrt(32)
        s[kk] = a;
        mx = fmaxf(mx, a);
    }
    float sum = 0.f;
    #pragma unroll
    for (int kk = 0; kk < 32; kk++) { float e = __expf(s[kk] - mx); s[kk] = e; sum += e; }
    float inv = 1.f / (sum * 32.f);      // softmax + mean over t folded
    // transposed store: s_sh[h][kk][t], pitch 33 -> conflict-free both ways
    float* s_sh = qbuf;
    #pragma unroll
    for (int kk = 0; kk < 32; kk++) s_sh[h * 1056 + kk * 33 + t] = s[kk] * inv;
    __syncthreads();

    // column reduction over t: thread (h=wid, kk=lane)
    {
        float ab = 0.f;
        #pragma unroll
        for (int tt = 0; tt < 32; tt++) ab += s_sh[wid * 1056 + lane * 33 + tt];
        abar_sh[wid * 32 + lane] = ab;
    }
    __syncthreads();

    // mean attention output channel c = tid
    float o = 0.f;
    #pragma unroll
    for (int kk = 0; kk < 32; kk++) o += abar_sh[(tid >> 5) * 32 + kk] * v_sh[kk * EMB + tid];
    oav[tid] = o;
    __syncthreads();

    // fused projection: pooled = Wf @ oav + bf   (warp-per-row, coalesced)
    #pragma unroll 4
    for (int r = 0; r < 32; r++) {
        int row = wid * 32 + r;
        const float* wr = g_wf + row * 128;
        float acc = wr[lane] * oav[lane] + wr[lane + 32] * oav[lane + 32]
                  + wr[lane + 64] * oav[lane + 64] + wr[lane + 96] * oav[lane + 96];
        acc = warp_reduce(acc);
        if (lane == 0) g_pooled[(size_t)n * EMB + row] = acc + g_bf[row];
    }
}

// ================= 4. Cross-attention (q-len 1, <=4 neighbors) + LayerNorm =========
__global__ __launch_bounds__(128) void cross_kernel(
    const float* __restrict__ ca_in_w, const float* __restrict__ ca_in_b,
    const float* __restrict__ ca_out_w, const float* __restrict__ ca_out_b,
    const float* __restrict__ lng, const float* __restrict__ lnb)
{
    int ci = blockIdx.x >> 8;     // weights reused across consecutive blocks
    int b  = blockIdx.x & 255;
    int tid = threadIdx.x;
    int wid = tid >> 5, lane = tid & 31;

    int left  = ci - 2 > 0 ? ci - 2 : 0;
    int right = ci + 3 < 64 ? ci + 3 : 64;
    int idx[4]; int nbr = 0;
    for (int i = left; i < right; i++) if (i != ci) idx[nbr++] = i;

    __shared__ float cen[128], ctx[4][128];
    __shared__ float q_sh[128], k_sh2[4][128], v_sh2[4][128];
    __shared__ float o_sh[128], sc_sh[16], a_w[16], r_sh[128], stats[2];

    cen[tid] = g_pooled[((size_t)b * 64 + ci) * 128 + tid];
    #pragma unroll
    for (int j = 0; j < 4; j++)
        ctx[j][tid] = (j < nbr) ? g_pooled[((size_t)b * 64 + idx[j]) * 128 + tid] : 0.f;
    __syncthreads();

    const float* Wbase = ca_in_w + (size_t)ci * 384 * 128;
    const float* bbase = ca_in_b + ci * 384;

    // --- Q rows (warp-per-row, coalesced weight loads) ---
    for (int r = 0; r < 32; r++) {
        int row = wid * 32 + r;
        const float* wr = Wbase + (size_t)row * 128;
        float acc = wr[lane] * cen[lane] + wr[lane + 32] * cen[lane + 32]
                  + wr[lane + 64] * cen[lane + 64] + wr[lane + 96] * cen[lane + 96];
        acc = warp_reduce(acc);
        if (lane == 0) q_sh[row] = acc + bbase[row];
    }
    // --- K rows (4 neighbor outputs per row) ---
    for (int r = 0; r < 32; r++) {
        int row = wid * 32 + r;
        const float* wr = Wbase + (size_t)(128 + row) * 128;
        float w0 = wr[lane], w1 = wr[lane + 32], w2 = wr[lane + 64], w3 = wr[lane + 96];
        float a0 = w0 * ctx[0][lane] + w1 * ctx[0][lane + 32] + w2 * ctx[0][lane + 64] + w3 * ctx[0][lane + 96];
        float a1 = w0 * ctx[1][lane] + w1 * ctx[1][lane + 32] + w2 * ctx[1][lane + 64] + w3 * ctx[1][lane + 96];
        float a2 = w0 * ctx[2][lane] + w1 * ctx[2][lane + 32] + w2 * ctx[2][lane + 64] + w3 * ctx[2][lane + 96];
        float a3 = w0 * ctx[3][lane] + w1 * ctx[3][lane + 32] + w2 * ctx[3][lane + 64] + w3 * ctx[3][lane + 96];
        a0 = warp_reduce(a0); a1 = warp_reduce(a1);
        a2 = warp_reduce(a2); a3 = warp_reduce(a3);
        if (lane == 0) {
            float bb = bbase[128 + row];
            k_sh2[0][row] = a0 + bb; k_sh2[1][row] = a1 + bb;
            k_sh2[2][row] = a2 + bb; k_sh2[3][row] = a3 + bb;
        }
    }
    // --- V rows ---
    for (int r = 0; r < 32; r++) {
        int row = wid * 32 + r;
        const float* wr = Wbase + (size_t)(256 + row) * 128;
        float w0 = wr[lane], w1 = wr[lane + 32], w2 = wr[lane + 64], w3 = wr[lane + 96];
        float a0 = w0 * ctx[0][lane] + w1 * ctx[0][lane + 32] + w2 * ctx[0][lane + 64] + w3 * ctx[0][lane + 96];
        float a1 = w0 * ctx[1][lane] + w1 * ctx[1][lane + 32] + w2 * ctx[1][lane + 64] + w3 * ctx[1][lane + 96];
        float a2 = w0 * ctx[2][lane] + w1 * ctx[2][lane + 32] + w2 * ctx[2][lane + 64] + w3 * ctx[2][lane + 96];
        float a3 = w0 * ctx[3][lane] + w1 * ctx[3][lane + 32] + w2 * ctx[3][lane + 64] + w3 * ctx[3][lane + 96];
        a0 = warp_reduce(a0); a1 = warp_reduce(a1);
        a2 = warp_reduce(a2); a3 = warp_reduce(a3);
        if (lane == 0) {
            float bb = bbase[256 + row];
            v_sh2[0][row] = a0 + bb; v_sh2[1][row] = a1 + bb;
            v_sh2[2][row] = a2 + bb; v_sh2[3][row] = a3 + bb;
        }
    }
    __syncthreads();

    // --- scores + softmax (4 heads x <=4 neighbors) ---
    if (tid < 16) {
        int h = tid >> 2, j = tid & 3;
        float sv = 0.f;
        if (j < nbr) {
            #pragma unroll
            for (int d = 0; d < 32; d++) sv += q_sh[h * 32 + d] * k_sh2[j][h * 32 + d];
            sv *= 0.1767766953f;
        }
        sc_sh[tid] = sv;
    }
    __syncthreads();
    if (tid < 4) {
        float mx = -1e30f;
        for (int j = 0; j < nbr; j++) mx = fmaxf(mx, sc_sh[tid * 4 + j]);
        float e[4]; float sum = 0.f;
        for (int j = 0; j < nbr; j++) { e[j] = __expf(sc_sh[tid * 4 + j] - mx); sum += e[j]; }
        #pragma unroll
        for (int j = 0; j < 4; j++) a_w[tid * 4 + j] = (j < nbr) ? e[j] / sum : 0.f;
    }
    __syncthreads();

    {
        int h = tid >> 5;
        float o = 0.f;
        #pragma unroll
        for (int j = 0; j < 4; j++) o += a_w[h * 4 + j] * v_sh2[j][tid];
        o_sh[tid] = o;
    }
    __syncthreads();

    // --- out-proj (warp-per-row, coalesced) + residual ---
    for (int r = 0; r < 32; r++) {
        int row = wid * 32 + r;
        const float* wr = ca_out_w + (size_t)ci * 16384 + (size_t)row * 128;
        float acc = wr[lane] * o_sh[lane] + wr[lane + 32] * o_sh[lane + 32]
                  + wr[lane + 64] * o_sh[lane + 64] + wr[lane + 96] * o_sh[lane + 96];
        acc = warp_reduce(acc);
        if (lane == 0) r_sh[row] = acc + ca_out_b[ci * 128 + row] + cen[row];
    }
    __syncthreads();

    // --- LayerNorm ---
    if (tid < 32) {
        float p = r_sh[tid] + r_sh[tid + 32] + r_sh[tid + 64] + r_sh[tid + 96];
        p = warp_reduce(p);
        if (tid == 0) stats[0] = p * (1.f / 128.f);
    }
    __syncthreads();
    float m = stats[0];
    if (tid < 32) {
        float d0 = r_sh[tid] - m, d1 = r_sh[tid + 32] - m;
        float d2 = r_sh[tid + 64] - m, d3 = r_sh[tid + 96] - m;
        float p = d0 * d0 + d1 * d1 + d2 * d2 + d3 * d3;
        p = warp_reduce(p);
        if (tid == 0) stats[1] = p * (1.f / 128.f);
    }
    __syncthreads();
    float yv = (r_sh[tid] - m) * rsqrtf(stats[1] + 1e-5f) * lng[ci * 128 + tid] + lnb[ci * 128 + tid];
    g_seq[(size_t)b * 8192 + ci * 128 + tid] = yv;
}

// ================= 5. Final MLP: relu(seq@fd1^T+b) @ fd2^T + b =====================
__global__ __launch_bounds__(256) void mlp_kernel(
    const float* __restrict__ fd1_w, const float* __restrict__ fd1_b,
    const float* __restrict__ fd2_w, const float* __restrict__ fd2_b,
    float* __restrict__ out)
{
    int b = blockIdx.x;
    int tid = threadIdx.x;
    __shared__ float s_sh[8192];
    __shared__ float h1[64];
    for (int i = tid; i < 8192; i += 256) s_sh[i] = g_seq[(size_t)b * 8192 + i];
    __syncthreads();

    int w = tid >> 5, l = tid & 31;
    for (int j = w; j < 64; j += 8) {
        float acc = 0.f;
        const float* row = fd1_w + (size_t)j * 8192;
        for (int c = l; c < 8192; c += 32) acc += row[c] * s_sh[c];
        acc = warp_reduce(acc);
        if (l == 0) h1[j] = fmaxf(acc + fd1_b[j], 0.f);
    }
    __syncthreads();
    if (tid < 5) {
        float o = fd2_b[tid];
        #pragma unroll
        for (int j = 0; j < 64; j++) o += fd2_w[tid * 64 + j] * h1[j];
        out[b * 5 + tid] = o;
    }
}

// =================================== launch ========================================
extern "C" void kernel_launch(void* const* d_in, const int* in_sizes, int n_in,
                              void* d_out, int out_size)
{
    const float* x        = (const float*)d_in[0];
    const float* wihf     = (const float*)d_in[1];
    const float* whhf     = (const float*)d_in[2];
    const float* bihf     = (const float*)d_in[3];
    const float* bhhf     = (const float*)d_in[4];
    const float* wihb     = (const float*)d_in[5];
    const float* whhb     = (const float*)d_in[6];
    const float* bihb     = (const float*)d_in[7];
    const float* bhhb     = (const float*)d_in[8];
    const float* sa_in_w  = (const float*)d_in[9];
    const float* sa_in_b  = (const float*)d_in[10];
    const float* sa_out_w = (const float*)d_in[11];
    const float* sa_out_b = (const float*)d_in[12];
    const float* proj_w   = (const float*)d_in[13];
    const float* proj_b   = (const float*)d_in[14];
    const float* ca_in_w  = (const float*)d_in[15];
    const float* ca_in_b  = (const float*)d_in[16];
    const float* ca_out_w = (const float*)d_in[17];
    const float* ca_out_b = (const float*)d_in[18];
    const float* ln_g     = (const float*)d_in[19];
    const float* ln_b     = (const float*)d_in[20];
    const float* fd1_w    = (const float*)d_in[21];
    const float* fd1_b    = (const float*)d_in[22];
    const float* fd2_w    = (const float*)d_in[23];
    const float* fd2_b    = (const float*)d_in[24];

    dim3 gp(80, 2);
    pack_kernel<<<gp, 128>>>(wihf, whhf, bihf, bhhf, wihb, whhb, bihb, bhhb);

    fuse_kernel<<<128, 128>>>(sa_out_w, sa_out_b, proj_w, proj_b);

    lstm_kernel<<<NWIN, 256>>>(x);

    dim3 g2(3, 4096);   // N tiles x M tiles; x-fastest keeps A-tiles hot in L2
    qkv_gemm<<<g2, 256>>>(sa_in_w, sa_in_b);

    attn_kernel<<<NWIN, 128>>>();

    cross_kernel<<<NWIN, 128>>>(ca_in_w, ca_in_b, ca_out_w, ca_out_b, ln_g, ln_b);

    mlp_kernel<<<256, 256>>>(fd1_w, fd1_b, fd2_w, fd2_b, (float*)d_out);
}

// round 17
// speedup vs baseline: 2.2856x; 1.0599x over previous
#include <cuda_runtime.h>

#define NWIN 16384      // B*NW = 256*64 windows
#define SEQT 32         // WIN
#define FEATN 16
#define HID 64
#define GATES 256       // 4*HID
#define EMB 128

typedef unsigned long long u64;

// -------- scratch (device globals: allocation-free rule) --------
__device__ float g_lo[(size_t)NWIN * SEQT * EMB];      // bilstm output, 268MB
__device__ float g_y1[(size_t)NWIN * SEQT * 384];      // q|k|v, 805MB
__device__ float g_pooled[(size_t)NWIN * EMB];         // 8MB
__device__ float g_seq[(size_t)256 * 8192];            // 8MB
__device__ float g_wf[128 * 128];                      // fused proj_w@out_w
__device__ float g_bf[128];                            // fused bias
__device__ u64   g_wpack[2 * 80 * 128];                // [dir][row][g2] packed lstm weights
__device__ u64   g_bias2[2 * 128];                     // packed lstm biases

__device__ __forceinline__ float sigmf(float x) { return 1.f / (1.f + __expf(-x)); }

__device__ __forceinline__ float warp_reduce(float v) {
    #pragma unroll
    for (int off = 16; off > 0; off >>= 1) v += __shfl_xor_sync(0xffffffffu, v, off);
    return v;
}

// ---- packed fp32x2 helpers (Blackwell FFMA2 path; ptxas never emits it itself) ----
__device__ __forceinline__ u64 pk(float lo, float hi) {
    u64 r; asm("mov.b64 %0, {%1, %2};" : "=l"(r) : "f"(lo), "f"(hi)); return r;
}
__device__ __forceinline__ void upk(u64 v, float& lo, float& hi) {
    asm("mov.b64 {%0, %1}, %2;" : "=f"(lo), "=f"(hi) : "l"(v));
}
__device__ __forceinline__ u64 fma2(u64 a, u64 b, u64 c) {
    u64 d; asm("fma.rn.f32x2 %0, %1, %2, %3;" : "=l"(d) : "l"(a), "l"(b), "l"(c)); return d;
}
__device__ __forceinline__ u64 add2(u64 a, u64 b) {
    u64 d; asm("add.rn.f32x2 %0, %1, %2;" : "=l"(d) : "l"(a), "l"(b)); return d;
}
__device__ __forceinline__ void bar_sync(int id, int nthr) {
    asm volatile("bar.sync %0, %1;" :: "r"(id), "r"(nthr) : "memory");
}

// ---- tf32 helpers ----
__device__ __forceinline__ unsigned f2tf(float x) {
    unsigned r; asm("cvt.rna.tf32.f32 %0, %1;" : "=r"(r) : "f"(x)); return r;
}
__device__ __forceinline__ void mma_tf32(float& d0, float& d1, float& d2, float& d3,
                                         unsigned a0, unsigned a1, unsigned a2, unsigned a3,
                                         unsigned b0, unsigned b1) {
    asm volatile(
        "mma.sync.aligned.m16n8k8.row.col.f32.tf32.tf32.f32 "
        "{%0,%1,%2,%3}, {%4,%5,%6,%7}, {%8,%9}, {%0,%1,%2,%3};\n"
        : "+f"(d0), "+f"(d1), "+f"(d2), "+f"(d3)
        : "r"(a0), "r"(a1), "r"(a2), "r"(a3), "r"(b0), "r"(b1));
}

// ======== 0. Pack LSTM weights: transposed so lstm loads are coalesced =============
__global__ __launch_bounds__(128) void pack_kernel(
    const float* __restrict__ wihf, const float* __restrict__ whhf,
    const float* __restrict__ bihf, const float* __restrict__ bhhf,
    const float* __restrict__ wihb, const float* __restrict__ whhb,
    const float* __restrict__ bihb, const float* __restrict__ bhhb)
{
    int r   = blockIdx.x;     // 0..79
    int dir = blockIdx.y;     // 0..1
    int g2  = threadIdx.x;    // 0..127
    const float* wih = dir ? wihb : wihf;
    const float* whh = dir ? whhb : whhf;
    const float* bih = dir ? bihb : bihf;
    const float* bhh = dir ? bhhb : bhhf;

    u64 v;
    if (r < 64) v = pk(whh[g2 * HID + r], whh[(g2 + 128) * HID + r]);
    else {
        int f = r - 64;
        v = pk(wih[g2 * FEATN + f], wih[(g2 + 128) * FEATN + f]);
    }
    g_wpack[dir * 10240 + r * 128 + g2] = v;
    if (r == 0)
        g_bias2[dir * 128 + g2] = pk(bih[g2] + bhh[g2], bih[g2 + 128] + bhh[g2 + 128]);
}

// ============ 1. BiLSTM: 256 thr/block, each thread owns gate pair (g, g+128) ======
__global__ __launch_bounds__(256) void lstm_kernel(const float* __restrict__ x)
{
    int n   = blockIdx.x;
    int tid = threadIdx.x;
    int dir = tid >> 7;     // 0=fwd, 1=bwd (warp-aligned split)
    int g2  = tid & 127;    // thread owns gates (g2, g2+128) -> (i,gg) or (f,o)

    __shared__ __align__(16) u64 xs2[SEQT * FEATN];   // (x,x) duplicated pairs
    __shared__ __align__(16) u64 h_sh[2][HID];        // (h,h) duplicated pairs
    __shared__ u64 g2sh[2][128];                      // raw gate pairs

    for (int i = tid; i < SEQT * FEATN; i += 256) {
        float v = x[(size_t)n * 512 + i];
        xs2[i] = pk(v, v);
    }

    const u64* wp = g_wpack + dir * 10240;
    u64 wh2[HID];
    #pragma unroll
    for (int k = 0; k < HID; k++) wh2[k] = wp[k * 128 + g2];
    u64 wi2[FEATN];
    #pragma unroll
    for (int f = 0; f < FEATN; f++) wi2[f] = wp[(64 + f) * 128 + g2];
    u64 bias2 = g_bias2[dir * 128 + g2];

    if (g2 < HID) h_sh[dir][g2] = 0ull;
    float c = 0.f;
    __syncthreads();

    for (int s = 0; s < SEQT; s++) {
        int t = dir ? (31 - s) : s;
        u64 a0 = bias2, a1 = 0ull, a2 = 0ull, a3 = 0ull;
        const ulonglong2* xp = (const ulonglong2*)&xs2[t * FEATN];
        #pragma unroll
        for (int f2 = 0; f2 < 8; f2 += 2) {
            ulonglong2 x0 = xp[f2], x1 = xp[f2 + 1];
            a0 = fma2(x0.x, wi2[2 * f2 + 0], a0);
            a1 = fma2(x0.y, wi2[2 * f2 + 1], a1);
            a2 = fma2(x1.x, wi2[2 * f2 + 2], a2);
            a3 = fma2(x1.y, wi2[2 * f2 + 3], a3);
        }
        const ulonglong2* hp = (const ulonglong2*)h_sh[dir];
        #pragma unroll
        for (int k2 = 0; k2 < 32; k2 += 2) {
            ulonglong2 h0 = hp[k2], h1 = hp[k2 + 1];
            a0 = fma2(h0.x, wh2[2 * k2 + 0], a0);
            a1 = fma2(h0.y, wh2[2 * k2 + 1], a1);
            a2 = fma2(h1.x, wh2[2 * k2 + 2], a2);
            a3 = fma2(h1.y, wh2[2 * k2 + 3], a3);
        }
        g2sh[dir][g2] = add2(add2(a0, a1), add2(a2, a3));
        bar_sync(dir + 1, 128);
        if (g2 < HID) {
            float iv, gv, fv, ov;
            upk(g2sh[dir][g2], iv, gv);          // gates (g2, g2+128) = (i, gg)
            upk(g2sh[dir][g2 + 64], fv, ov);     // gates (g2+64, g2+192) = (f, o)
            iv = sigmf(iv); fv = sigmf(fv);
            gv = tanhf(gv); ov = sigmf(ov);
            c = fv * c + iv * gv;
            float h = ov * tanhf(c);
            h_sh[dir][g2] = pk(h, h);
            g_lo[((size_t)n * SEQT + t) * EMB + dir * HID + g2] = h;
        }
        bar_sync(dir + 1, 128);
    }
}

// ============ 1b. Fuse out_w/proj_w: Wf = proj_w@out_w, bf = proj_w@out_b+proj_b ===
__global__ __launch_bounds__(128) void fuse_kernel(
    const float* __restrict__ out_w, const float* __restrict__ out_b,
    const float* __restrict__ proj_w, const float* __restrict__ proj_b)
{
    int i = blockIdx.x;     // output row
    int c = threadIdx.x;    // output col
    float acc = 0.f;
    #pragma unroll 8
    for (int j = 0; j < 128; j++) acc += proj_w[i * 128 + j] * out_w[j * 128 + c];
    g_wf[i * 128 + c] = acc;
    if (c == 0) {
        float s = proj_b[i];
        for (int j = 0; j < 128; j++) s += proj_w[i * 128 + j] * out_b[j];
        g_bf[i] = s;
    }
}

// ================= 2. QKV GEMM via tensor cores (3xTF32, mma.sync m16n8k8) =========
// Block tile 128(M)x64(N), K chunked by 16. 8 warps = 4m x 2n, warp tile 32x32.
// hi/lo tf32 split done at staging; inner loop = conflict-free LDS + MMA.
__global__ __launch_bounds__(256, 2) void qkv_gemm(const float* __restrict__ W,
                                                   const float* __restrict__ bias)
{
    // pitch 20 words: r*20 mod 32 is a permutation over 8 row-groups -> conflict-free frags
    __shared__ unsigned As_h[128][20], As_l[128][20];
    __shared__ unsigned Bs_h[64][20],  Bs_l[64][20];

    int m0 = blockIdx.y * 128;
    int n0 = blockIdx.x * 64;
    int tid = threadIdx.x;
    int wid = tid >> 5, lane = tid & 31;
    int wm = wid & 3;            // 0..3 -> m offset wm*32
    int wn = wid >> 2;           // 0..1 -> n offset wn*32
    int g  = lane >> 2;          // group id 0..7
    int tg = lane & 3;           // thread-in-group 0..3

    // staging assignment
    int arow = tid >> 1;                 // 0..127
    int acb  = (tid & 1) * 8;            // col base 0/8
    int brow = tid >> 2;                 // 0..63
    int bcb  = (tid & 3) * 4;            // col base 0/4/8/12

    const float* aptr = &g_lo[(size_t)(m0 + arow) * 128 + acb];
    const float* bptr = &W[(size_t)(n0 + brow) * 128 + bcb];

    float acc[2][4][4];
    #pragma unroll
    for (int mt = 0; mt < 2; mt++)
        #pragma unroll
        for (int nt = 0; nt < 4; nt++)
            #pragma unroll
            for (int i = 0; i < 4; i++) acc[mt][nt][i] = 0.f;

    // prologue: load chunk 0
    float4 va0 = *(const float4*)(aptr);
    float4 va1 = *(const float4*)(aptr + 4);
    float4 vb  = *(const float4*)(bptr);

    #pragma unroll
    for (int ch = 0; ch < 8; ch++) {
        // ---- stage current chunk with hi/lo tf32 split ----
        {
            float av[8] = {va0.x, va0.y, va0.z, va0.w, va1.x, va1.y, va1.z, va1.w};
            #pragma unroll
            for (int i = 0; i < 8; i++) {
                unsigned h = f2tf(av[i]);
                As_h[arow][acb + i] = h;
                As_l[arow][acb + i] = f2tf(av[i] - __uint_as_float(h));
            }
            float bv[4] = {vb.x, vb.y, vb.z, vb.w};
            #pragma unroll
            for (int i = 0; i < 4; i++) {
                unsigned h = f2tf(bv[i]);
                Bs_h[brow][bcb + i] = h;
                Bs_l[brow][bcb + i] = f2tf(bv[i] - __uint_as_float(h));
            }
        }
        __syncthreads();

        // ---- prefetch next chunk (overlaps MMA below) ----
        if (ch < 7) {
            int kt = (ch + 1) * 16;
            va0 = *(const float4*)(aptr + kt);
            va1 = *(const float4*)(aptr + kt + 4);
            vb  = *(const float4*)(bptr + kt);
        }

        // ---- 2 k-steps of m16n8k8 ----
        #pragma unroll
        for (int ks = 0; ks < 2; ks++) {
            int k0 = ks * 8 + tg;
            unsigned ah[2][4], al[2][4];
            #pragma unroll
            for (int mt = 0; mt < 2; mt++) {
                int r = wm * 32 + mt * 16 + g;
                ah[mt][0] = As_h[r][k0];     ah[mt][1] = As_h[r + 8][k0];
                ah[mt][2] = As_h[r][k0 + 4]; ah[mt][3] = As_h[r + 8][k0 + 4];
                al[mt][0] = As_l[r][k0];     al[mt][1] = As_l[r + 8][k0];
                al[mt][2] = As_l[r][k0 + 4]; al[mt][3] = As_l[r + 8][k0 + 4];
            }
            unsigned bh[4][2], bl[4][2];
            #pragma unroll
            for (int nt = 0; nt < 4; nt++) {
                int nn = wn * 32 + nt * 8 + g;
                bh[nt][0] = Bs_h[nn][k0];     bh[nt][1] = Bs_h[nn][k0 + 4];
                bl[nt][0] = Bs_l[nn][k0];     bl[nt][1] = Bs_l[nn][k0 + 4];
            }
            #pragma unroll
            for (int mt = 0; mt < 2; mt++)
                #pragma unroll
                for (int nt = 0; nt < 4; nt++) {
                    float* d = acc[mt][nt];
                    mma_tf32(d[0], d[1], d[2], d[3],
                             ah[mt][0], ah[mt][1], ah[mt][2], ah[mt][3],
                             bh[nt][0], bh[nt][1]);
                    mma_tf32(d[0], d[1], d[2], d[3],
                             ah[mt][0], ah[mt][1], ah[mt][2], ah[mt][3],
                             bl[nt][0], bl[nt][1]);
                    mma_tf32(d[0], d[1], d[2], d[3],
                             al[mt][0], al[mt][1], al[mt][2], al[mt][3],
                             bh[nt][0], bh[nt][1]);
                }
        }
        __syncthreads();
    }

    // ---- epilogue: bias + direct global store (float2, sector-friendly) ----
    #pragma unroll
    for (int nt = 0; nt < 4; nt++) {
        int nn = n0 + wn * 32 + nt * 8 + 2 * tg;
        float2 bv = *(const float2*)&bias[nn];
        #pragma unroll
        for (int mt = 0; mt < 2; mt++) {
            int r0 = m0 + wm * 32 + mt * 16 + g;
            float2 o0 = make_float2(acc[mt][nt][0] + bv.x, acc[mt][nt][1] + bv.y);
            float2 o1 = make_float2(acc[mt][nt][2] + bv.x, acc[mt][nt][3] + bv.y);
            *(float2*)&g_y1[(size_t)r0 * 384 + nn]       = o0;
            *(float2*)&g_y1[(size_t)(r0 + 8) * 384 + nn] = o1;
        }
    }
}

// ===== 3. Self-attn + fused out/proj + mean-pool (mean-commute trick) ==============
__global__ __launch_bounds__(128) void attn_kernel()
{
    int n = blockIdx.x;
    int tid = threadIdx.x;
    int wid = tid >> 5, lane = tid & 31;
    __shared__ float qbuf[32 * 133];     // q staging; later reused as score matrix
    __shared__ float k_sh[SEQT * EMB];
    __shared__ float v_sh[SEQT * EMB];
    __shared__ float abar_sh[EMB];       // [h*32 + k]: mean_t softmax weights
    __shared__ float oav[EMB];

    const float* y = g_y1 + (size_t)n * SEQT * 384;
    for (int i4 = tid; i4 < 3072; i4 += 128) {
        int t = i4 / 96;                 // 96 float4 per token row
        int c = (i4 - t * 96) * 4;
        float4 v = ((const float4*)y)[i4];
        if (c < 128) {
            float* q = &qbuf[t * 133 + c];
            q[0] = v.x; q[1] = v.y; q[2] = v.z; q[3] = v.w;
        } else if (c < 256) {
            *(float4*)&k_sh[t * 128 + (c - 128)] = v;
        } else {
            *(float4*)&v_sh[t * 128 + (c - 256)] = v;
        }
    }
    __syncthreads();

    int h = wid, t = lane;               // one (head, query-token) row per thread
    u64 q2[16];
    #pragma unroll
    for (int d2 = 0; d2 < 16; d2++)
        q2[d2] = pk(qbuf[t * 133 + h * 32 + 2 * d2], qbuf[t * 133 + h * 32 + 2 * d2 + 1]);
    __syncthreads();                     // qbuf now dead -> reuse as score matrix

    float s[32];
    float mx = -1e30f;
    #pragma unroll
    for (int kk = 0; kk < 32; kk++) {
        const ulonglong2* kp2 = (const ulonglong2*)&k_sh[kk * EMB + h * 32];
        u64 accA = 0ull, accB = 0ull;
        #pragma unroll
        for (int d4 = 0; d4 < 8; d4++) {
            ulonglong2 kv = kp2[d4];
            accA = fma2(kv.x, q2[2 * d4], accA);
            accB = fma2(kv.y, q2[2 * d4 + 1], accB);
        }
        float lo, hi; upk(add2(accA, accB), lo, hi);
        float a = (lo + hi) * 0.1767766953f;   // 1/sqrt(32)
        s[kk] = a;
        mx = fmaxf(mx, a);
    }
    float sum = 0.f;
    #pragma unroll
    for (int kk = 0; kk < 32; kk++) { float e = __expf(s[kk] - mx); s[kk] = e; sum += e; }
    float inv = 1.f / (sum * 32.f);      // softmax + mean over t folded
    float* s_sh = qbuf;
    #pragma unroll
    for (int kk = 0; kk < 32; kk++) s_sh[h * 1056 + kk * 33 + t] = s[kk] * inv;
    __syncthreads();

    {
        float ab = 0.f;
        #pragma unroll
        for (int tt = 0; tt < 32; tt++) ab += s_sh[wid * 1056 + lane * 33 + tt];
        abar_sh[wid * 32 + lane] = ab;
    }
    __syncthreads();

    float o = 0.f;
    #pragma unroll
    for (int kk = 0; kk < 32; kk++) o += abar_sh[(tid >> 5) * 32 + kk] * v_sh[kk * EMB + tid];
    oav[tid] = o;
    __syncthreads();

    #pragma unroll 4
    for (int r = 0; r < 32; r++) {
        int row = wid * 32 + r;
        const float* wr = g_wf + row * 128;
        float acc = wr[lane] * oav[lane] + wr[lane + 32] * oav[lane + 32]
                  + wr[lane + 64] * oav[lane + 64] + wr[lane + 96] * oav[lane + 96];
        acc = warp_reduce(acc);
        if (lane == 0) g_pooled[(size_t)n * EMB + row] = acc + g_bf[row];
    }
}

// ================= 4. Cross-attention (q-len 1, <=4 neighbors) + LayerNorm =========
__global__ __launch_bounds__(128) void cross_kernel(
    const float* __restrict__ ca_in_w, const float* __restrict__ ca_in_b,
    const float* __restrict__ ca_out_w, const float* __restrict__ ca_out_b,
    const float* __restrict__ lng, const float* __restrict__ lnb)
{
    int ci = blockIdx.x >> 8;     // weights reused across consecutive blocks
    int b  = blockIdx.x & 255;
    int tid = threadIdx.x;
    int wid = tid >> 5, lane = tid & 31;

    int left  = ci - 2 > 0 ? ci - 2 : 0;
    int right = ci + 3 < 64 ? ci + 3 : 64;
    int idx[4]; int nbr = 0;
    for (int i = left; i < right; i++) if (i != ci) idx[nbr++] = i;

    __shared__ float cen[128], ctx[4][128];
    __shared__ float q_sh[128], k_sh2[4][128], v_sh2[4][128];
    __shared__ float o_sh[128], sc_sh[16], a_w[16], r_sh[128], stats[2];

    cen[tid] = g_pooled[((size_t)b * 64 + ci) * 128 + tid];
    #pragma unroll
    for (int j = 0; j < 4; j++)
        ctx[j][tid] = (j < nbr) ? g_pooled[((size_t)b * 64 + idx[j]) * 128 + tid] : 0.f;
    __syncthreads();

    const float* Wbase = ca_in_w + (size_t)ci * 384 * 128;
    const float* bbase = ca_in_b + ci * 384;

    for (int r = 0; r < 32; r++) {
        int row = wid * 32 + r;
        const float* wr = Wbase + (size_t)row * 128;
        float acc = wr[lane] * cen[lane] + wr[lane + 32] * cen[lane + 32]
                  + wr[lane + 64] * cen[lane + 64] + wr[lane + 96] * cen[lane + 96];
        acc = warp_reduce(acc);
        if (lane == 0) q_sh[row] = acc + bbase[row];
    }
    for (int r = 0; r < 32; r++) {
        int row = wid * 32 + r;
        const float* wr = Wbase + (size_t)(128 + row) * 128;
        float w0 = wr[lane], w1 = wr[lane + 32], w2 = wr[lane + 64], w3 = wr[lane + 96];
        float a0 = w0 * ctx[0][lane] + w1 * ctx[0][lane + 32] + w2 * ctx[0][lane + 64] + w3 * ctx[0][lane + 96];
        float a1 = w0 * ctx[1][lane] + w1 * ctx[1][lane + 32] + w2 * ctx[1][lane + 64] + w3 * ctx[1][lane + 96];
        float a2 = w0 * ctx[2][lane] + w1 * ctx[2][lane + 32] + w2 * ctx[2][lane + 64] + w3 * ctx[2][lane + 96];
        float a3 = w0 * ctx[3][lane] + w1 * ctx[3][lane + 32] + w2 * ctx[3][lane + 64] + w3 * ctx[3][lane + 96];
        a0 = warp_reduce(a0); a1 = warp_reduce(a1);
        a2 = warp_reduce(a2); a3 = warp_reduce(a3);
        if (lane == 0) {
            float bb = bbase[128 + row];
            k_sh2[0][row] = a0 + bb; k_sh2[1][row] = a1 + bb;
            k_sh2[2][row] = a2 + bb; k_sh2[3][row] = a3 + bb;
        }
    }
    for (int r = 0; r < 32; r++) {
        int row = wid * 32 + r;
        const float* wr = Wbase + (size_t)(256 + row) * 128;
        float w0 = wr[lane], w1 = wr[lane + 32], w2 = wr[lane + 64], w3 = wr[lane + 96];
        float a0 = w0 * ctx[0][lane] + w1 * ctx[0][lane + 32] + w2 * ctx[0][lane + 64] + w3 * ctx[0][lane + 96];
        float a1 = w0 * ctx[1][lane] + w1 * ctx[1][lane + 32] + w2 * ctx[1][lane + 64] + w3 * ctx[1][lane + 96];
        float a2 = w0 * ctx[2][lane] + w1 * ctx[2][lane + 32] + w2 * ctx[2][lane + 64] + w3 * ctx[2][lane + 96];
        float a3 = w0 * ctx[3][lane] + w1 * ctx[3][lane + 32] + w2 * ctx[3][lane + 64] + w3 * ctx[3][lane + 96];
        a0 = warp_reduce(a0); a1 = warp_reduce(a1);
        a2 = warp_reduce(a2); a3 = warp_reduce(a3);
        if (lane == 0) {
            float bb = bbase[256 + row];
            v_sh2[0][row] = a0 + bb; v_sh2[1][row] = a1 + bb;
            v_sh2[2][row] = a2 + bb; v_sh2[3][row] = a3 + bb;
        }
    }
    __syncthreads();

    if (tid < 16) {
        int h = tid >> 2, j = tid & 3;
        float sv = 0.f;
        if (j < nbr) {
            #pragma unroll
            for (int d = 0; d < 32; d++) sv += q_sh[h * 32 + d] * k_sh2[j][h * 32 + d];
            sv *= 0.1767766953f;
        }
        sc_sh[tid] = sv;
    }
    __syncthreads();
    if (tid < 4) {
        float mx = -1e30f;
        for (int j = 0; j < nbr; j++) mx = fmaxf(mx, sc_sh[tid * 4 + j]);
        float e[4]; float sum = 0.f;
        for (int j = 0; j < nbr; j++) { e[j] = __expf(sc_sh[tid * 4 + j] - mx); sum += e[j]; }
        #pragma unroll
        for (int j = 0; j < 4; j++) a_w[tid * 4 + j] = (j < nbr) ? e[j] / sum : 0.f;
    }
    __syncthreads();

    {
        int h = tid >> 5;
        float o = 0.f;
        #pragma unroll
        for (int j = 0; j < 4; j++) o += a_w[h * 4 + j] * v_sh2[j][tid];
        o_sh[tid] = o;
    }
    __syncthreads();

    for (int r = 0; r < 32; r++) {
        int row = wid * 32 + r;
        const float* wr = ca_out_w + (size_t)ci * 16384 + (size_t)row * 128;
        float acc = wr[lane] * o_sh[lane] + wr[lane + 32] * o_sh[lane + 32]
                  + wr[lane + 64] * o_sh[lane + 64] + wr[lane + 96] * o_sh[lane + 96];
        acc = warp_reduce(acc);
        if (lane == 0) r_sh[row] = acc + ca_out_b[ci * 128 + row] + cen[row];
    }
    __syncthreads();

    if (tid < 32) {
        float p = r_sh[tid] + r_sh[tid + 32] + r_sh[tid + 64] + r_sh[tid + 96];
        p = warp_reduce(p);
        if (tid == 0) stats[0] = p * (1.f / 128.f);
    }
    __syncthreads();
    float m = stats[0];
    if (tid < 32) {
        float d0 = r_sh[tid] - m, d1 = r_sh[tid + 32] - m;
        float d2 = r_sh[tid + 64] - m, d3 = r_sh[tid + 96] - m;
        float p = d0 * d0 + d1 * d1 + d2 * d2 + d3 * d3;
        p = warp_reduce(p);
        if (tid == 0) stats[1] = p * (1.f / 128.f);
    }
    __syncthreads();
    float yv = (r_sh[tid] - m) * rsqrtf(stats[1] + 1e-5f) * lng[ci * 128 + tid] + lnb[ci * 128 + tid];
    g_seq[(size_t)b * 8192 + ci * 128 + tid] = yv;
}

// ================= 5. Final MLP: relu(seq@fd1^T+b) @ fd2^T + b =====================
__global__ __launch_bounds__(256) void mlp_kernel(
    const float* __restrict__ fd1_w, const float* __restrict__ fd1_b,
    const float* __restrict__ fd2_w, const float* __restrict__ fd2_b,
    float* __restrict__ out)
{
    int b = blockIdx.x;
    int tid = threadIdx.x;
    __shared__ float s_sh[8192];
    __shared__ float h1[64];
    for (int i = tid; i < 8192; i += 256) s_sh[i] = g_seq[(size_t)b * 8192 + i];
    __syncthreads();

    int w = tid >> 5, l = tid & 31;
    for (int j = w; j < 64; j += 8) {
        float acc = 0.f;
        const float* row = fd1_w + (size_t)j * 8192;
        for (int c = l; c < 8192; c += 32) acc += row[c] * s_sh[c];
        acc = warp_reduce(acc);
        if (l == 0) h1[j] = fmaxf(acc + fd1_b[j], 0.f);
    }
    __syncthreads();
    if (tid < 5) {
        float o = fd2_b[tid];
        #pragma unroll
        for (int j = 0; j < 64; j++) o += fd2_w[tid * 64 + j] * h1[j];
        out[b * 5 + tid] = o;
    }
}

// =================================== launch ========================================
extern "C" void kernel_launch(void* const* d_in, const int* in_sizes, int n_in,
                              void* d_out, int out_size)
{
    const float* x        = (const float*)d_in[0];
    const float* wihf     = (const float*)d_in[1];
    const float* whhf     = (const float*)d_in[2];
    const float* bihf     = (const float*)d_in[3];
    const float* bhhf     = (const float*)d_in[4];
    const float* wihb     = (const float*)d_in[5];
    const float* whhb     = (const float*)d_in[6];
    const float* bihb     = (const float*)d_in[7];
    const float* bhhb     = (const float*)d_in[8];
    const float* sa_in_w  = (const float*)d_in[9];
    const float* sa_in_b  = (const float*)d_in[10];
    const float* sa_out_w = (const float*)d_in[11];
    const float* sa_out_b = (const float*)d_in[12];
    const float* proj_w   = (const float*)d_in[13];
    const float* proj_b   = (const float*)d_in[14];
    const float* ca_in_w  = (const float*)d_in[15];
    const float* ca_in_b  = (const float*)d_in[16];
    const float* ca_out_w = (const float*)d_in[17];
    const float* ca_out_b = (const float*)d_in[18];
    const float* ln_g     = (const float*)d_in[19];
    const float* ln_b     = (const float*)d_in[20];
    const float* fd1_w    = (const float*)d_in[21];
    const float* fd1_b    = (const float*)d_in[22];
    const float* fd2_w    = (const float*)d_in[23];
    const float* fd2_b    = (const float*)d_in[24];

    dim3 gp(80, 2);
    pack_kernel<<<gp, 128>>>(wihf, whhf, bihf, bhhf, wihb, whhb, bihb, bhhb);

    fuse_kernel<<<128, 128>>>(sa_out_w, sa_out_b, proj_w, proj_b);

    lstm_kernel<<<NWIN, 256>>>(x);

    dim3 g2(6, 4096);   // N tiles (64-wide) x M tiles (128-tall)
    qkv_gemm<<<g2, 256>>>(sa_in_w, sa_in_b);

    attn_kernel<<<NWIN, 128>>>();

    cross_kernel<<<NWIN, 128>>>(ca_in_w, ca_in_b, ca_out_w, ca_out_b, ln_g, ln_b);

    mlp_kernel<<<256, 256>>>(fd1_w, fd1_b, fd2_w, fd2_b, (float*)d_out);
}